// round 2
// baseline (speedup 1.0000x reference)
#include <cuda_runtime.h>
#include <cstdint>

#define NPTS   65536
#define DIMS   384
#define NK     64
#define ITERS  10
#define KC     32
#define NCH    12          // DIMS / KC
#define ACC_CTAS 128
#define ACC_PTS  512       // points per accumulation CTA

typedef unsigned long long u64;

// ---------------- scratch (device globals; no runtime allocation) ----------
__device__ float g_xt[(size_t)DIMS * NPTS];          // x transposed [D][N]
__device__ float g_centers[NK * DIMS];               // [K][D]
__device__ float g_centers_t[DIMS * NK];             // [D][K]
__device__ float g_cc[NK];                           // ||c_k||^2
__device__ int   g_labels[NPTS];
__device__ float g_partials[(size_t)ACC_CTAS * NK * DIMS];
__device__ float g_pcounts[ACC_CTAS * NK];
__device__ float g_proj[NK * DIMS];                  // centers @ W^T + b

// ---------------- PTX helpers ----------------------------------------------
__device__ __forceinline__ u64 f32x2_fma(u64 a, u64 b, u64 c) {
    u64 d;
    asm("fma.rn.f32x2 %0, %1, %2, %3;" : "=l"(d) : "l"(a), "l"(b), "l"(c));
    return d;
}
__device__ __forceinline__ u64 dup2(float f) {
    unsigned u = __float_as_uint(f);
    u64 r;
    asm("mov.b64 %0, {%1, %1};" : "=l"(r) : "r"(u));
    return r;
}
__device__ __forceinline__ void unpack2(u64 v, float& lo, float& hi) {
    unsigned a, b;
    asm("mov.b64 {%0, %1}, %2;" : "=r"(a), "=r"(b) : "l"(v));
    lo = __uint_as_float(a);
    hi = __uint_as_float(b);
}
__device__ __forceinline__ void cp16(void* smem, const void* gmem) {
    unsigned sa = (unsigned)__cvta_generic_to_shared(smem);
    asm volatile("cp.async.cg.shared.global [%0], [%1], 16;" :: "r"(sa), "l"(gmem));
}
__device__ __forceinline__ void cp_commit() {
    asm volatile("cp.async.commit_group;");
}
template <int N>
__device__ __forceinline__ void cp_wait() {
    asm volatile("cp.async.wait_group %0;" :: "n"(N));
}

// ---------------- transpose x[N][D] -> g_xt[D][N] --------------------------
__global__ void transpose_kernel(const float* __restrict__ x) {
    __shared__ float tile[32][33];
    int d0 = blockIdx.x * 32;
    int p0 = blockIdx.y * 32;
    int tx = threadIdx.x, ty = threadIdx.y;
#pragma unroll
    for (int j = 0; j < 32; j += 8)
        tile[ty + j][tx] = x[(size_t)(p0 + ty + j) * DIMS + d0 + tx];
    __syncthreads();
#pragma unroll
    for (int j = 0; j < 32; j += 8)
        g_xt[(size_t)(d0 + ty + j) * NPTS + p0 + tx] = tile[tx][ty + j];
}

// ---------------- init centers = first 64 points ---------------------------
__global__ void init_centers_kernel(const float* __restrict__ x) {
    __shared__ float red[DIMS];
    int k = blockIdx.x, d = threadIdx.x;
    float v = x[k * DIMS + d];
    g_centers[k * DIMS + d] = v;
    g_centers_t[d * NK + k] = v;
    red[d] = v * v;
    __syncthreads();
    for (int s = 256; s > 0; s >>= 1) {
        if (d < s && d + s < DIMS) red[d] += red[d + s];
        __syncthreads();
    }
    if (d == 0) g_cc[k] = red[0];
}

// ---------------- assignment -----------------------------------------------
// 256 CTAs x 256 threads; CTA tile = 256 points x 64 clusters.
// Thread tile: 8 points x 8 clusters (4 cluster-pairs as f32x2).
extern __shared__ float asg_smem[];

__device__ __forceinline__ void asg_prefetch(float* xs, float* cs, int buf,
                                             int kbase, unsigned pcta, int tid) {
#pragma unroll
    for (int j = 0; j < 8; ++j) {              // 2048 float4 for x tile (32KB)
        int id = j * 256 + tid;
        int r = id >> 6, c = (id & 63) << 2;
        cp16(&xs[buf * (KC * 256) + r * 256 + c],
             &g_xt[(size_t)(kbase + r) * NPTS + pcta + c]);
    }
#pragma unroll
    for (int j = 0; j < 2; ++j) {              // 512 float4 for centers tile (8KB)
        int id = j * 256 + tid;
        int r = id >> 4, c = (id & 15) << 2;
        cp16(&cs[buf * (KC * NK) + r * NK + c],
             &g_centers_t[(kbase + r) * NK + c]);
    }
    cp_commit();
}

__global__ void __launch_bounds__(256, 2) assign_kernel() {
    float* xs = asg_smem;                       // [2][KC][256]
    float* cs = asg_smem + 2 * KC * 256;        // [2][KC][64]

    const int tid  = threadIdx.x;
    const int warp = tid >> 5, lane = tid & 31;
    const int mg = lane >> 3, ng = lane & 7;
    const int prow  = warp * 32 + mg * 8;       // first of 8 points (in tile)
    const int nbase = ng * 8;                   // first of 8 clusters
    const unsigned pcta = blockIdx.x * 256u;

    asg_prefetch(xs, cs, 0, 0, pcta, tid);

    u64 acc[8][4];
#pragma unroll
    for (int m = 0; m < 8; ++m)
#pragma unroll
        for (int j = 0; j < 4; ++j) acc[m][j] = 0ull;

    for (int kc = 0; kc < NCH; ++kc) {
        const int buf = kc & 1;
        if (kc + 1 < NCH) {
            asg_prefetch(xs, cs, buf ^ 1, (kc + 1) * KC, pcta, tid);
            cp_wait<1>();
        } else {
            cp_wait<0>();
        }
        __syncthreads();

        const float* xr = xs + buf * (KC * 256);
        const float* cr = cs + buf * (KC * NK);
#pragma unroll 8
        for (int k = 0; k < KC; ++k) {
            const float4 xa = *reinterpret_cast<const float4*>(&xr[(k << 8) + prow]);
            const float4 xb = *reinterpret_cast<const float4*>(&xr[(k << 8) + prow + 4]);
            const ulonglong2 c01 = *reinterpret_cast<const ulonglong2*>(&cr[(k << 6) + nbase]);
            const ulonglong2 c23 = *reinterpret_cast<const ulonglong2*>(&cr[(k << 6) + nbase + 4]);
            const float xv[8] = {xa.x, xa.y, xa.z, xa.w, xb.x, xb.y, xb.z, xb.w};
#pragma unroll
            for (int m = 0; m < 8; ++m) {
                const u64 xd = dup2(xv[m]);
                acc[m][0] = f32x2_fma(xd, c01.x, acc[m][0]);
                acc[m][1] = f32x2_fma(xd, c01.y, acc[m][1]);
                acc[m][2] = f32x2_fma(xd, c23.x, acc[m][2]);
                acc[m][3] = f32x2_fma(xd, c23.y, acc[m][3]);
            }
        }
        __syncthreads();
    }

    // epilogue: dist = ||c||^2 - 2*dot ; argmin with lowest-index tiebreak
    float cn[8];
#pragma unroll
    for (int n = 0; n < 8; ++n) cn[n] = g_cc[nbase + n];

#pragma unroll
    for (int m = 0; m < 8; ++m) {
        float best = __int_as_float(0x7f800000);   // +inf
        int bi = NK;
#pragma unroll
        for (int j = 0; j < 4; ++j) {
            float v0, v1;
            unpack2(acc[m][j], v0, v1);
            const float s0 = fmaf(-2.0f, v0, cn[2 * j]);
            const float s1 = fmaf(-2.0f, v1, cn[2 * j + 1]);
            const int i0 = nbase + 2 * j, i1 = i0 + 1;
            if (s0 < best || (s0 == best && i0 < bi)) { best = s0; bi = i0; }
            if (s1 < best || (s1 == best && i1 < bi)) { best = s1; bi = i1; }
        }
#pragma unroll
        for (int off = 1; off < 8; off <<= 1) {
            const float ob = __shfl_xor_sync(0xffffffffu, best, off);
            const int   oi = __shfl_xor_sync(0xffffffffu, bi, off);
            if (ob < best || (ob == best && oi < bi)) { best = ob; bi = oi; }
        }
        if (ng == 0) g_labels[pcta + prow + m] = bi;
    }
}

// ---------------- segment-sum accumulation ---------------------------------
// 768 threads: two 384-thread groups (copies), each with a full 64x384 smem
// sum array. Copy c handles a distinct half of the CTA's 512 points; thread t
// owns dim t, so all smem RMWs hit distinct banks and no atomics are needed.
extern __shared__ float acc_smem[];
__global__ void __launch_bounds__(768, 1) accum_kernel() {
    __shared__ int   s_lb[ACC_PTS];
    __shared__ float s_cnt[2][NK];
    const int tid  = threadIdx.x;
    const int copy = (tid >= DIMS) ? 1 : 0;
    const int t    = tid - copy * DIMS;               // 0..383
    float* my = acc_smem + copy * (NK * DIMS);

    for (int i = tid; i < 2 * NK * DIMS; i += 768) acc_smem[i] = 0.f;
    const int pbase = blockIdx.x * ACC_PTS;
    if (tid < ACC_PTS) s_lb[tid] = g_labels[pbase + tid];
    __syncthreads();

    const int p0 = pbase + copy * (ACC_PTS / 2);
    const int l0 = copy * (ACC_PTS / 2);
    const float* xrow = g_xt + (size_t)t * NPTS + p0;
    float cnt = 0.f;

    for (int j = 0; j < (ACC_PTS / 2) / 8; ++j) {
        const float4 a = *reinterpret_cast<const float4*>(xrow + j * 8);
        const float4 b = *reinterpret_cast<const float4*>(xrow + j * 8 + 4);
        const float v[8] = {a.x, a.y, a.z, a.w, b.x, b.y, b.z, b.w};
#pragma unroll
        for (int i = 0; i < 8; ++i) {
            const int lb = s_lb[l0 + j * 8 + i];
            my[lb * DIMS + t] += v[i];
            cnt += (lb == t) ? 1.f : 0.f;   // only meaningful for t < 64
        }
    }
    if (t < NK) s_cnt[copy][t] = cnt;
    __syncthreads();

    float* outp = g_partials + (size_t)blockIdx.x * (NK * DIMS);
    for (int i = tid; i < NK * DIMS; i += 768)
        outp[i] = acc_smem[i] + acc_smem[i + NK * DIMS];
    if (tid < NK) g_pcounts[blockIdx.x * NK + tid] = s_cnt[0][tid] + s_cnt[1][tid];
}

// ---------------- center update + ||c||^2 ----------------------------------
__global__ void update_kernel() {
    __shared__ float red[DIMS];
    const int k = blockIdx.x, t = threadIdx.x;
    float sum = 0.f, cnt = 0.f;
    for (int c = 0; c < ACC_CTAS; ++c) {
        sum += g_partials[(size_t)c * (NK * DIMS) + k * DIMS + t];
        cnt += g_pcounts[c * NK + k];
    }
    const float v = (cnt > 0.f) ? (sum / fmaxf(cnt, 1.f)) : g_centers[k * DIMS + t];
    g_centers[k * DIMS + t] = v;
    g_centers_t[t * NK + k] = v;
    red[t] = v * v;
    __syncthreads();
    for (int s = 256; s > 0; s >>= 1) {
        if (t < s && t + s < DIMS) red[t] += red[t + s];
        __syncthreads();
    }
    if (t == 0) g_cc[k] = red[0];
}

// ---------------- proj = centers @ W^T + b ---------------------------------
__global__ void proj_kernel(const float* __restrict__ W, const float* __restrict__ b) {
    __shared__ float cs[DIMS];
    const int k = blockIdx.x, d = threadIdx.x;
    cs[d] = g_centers[k * DIMS + d];
    __syncthreads();
    const float4* Wr = reinterpret_cast<const float4*>(W + (size_t)d * DIMS);
    float acc = 0.f;
#pragma unroll 4
    for (int i = 0; i < DIMS / 4; ++i) {
        const float4 w = Wr[i];
        acc += cs[4 * i] * w.x + cs[4 * i + 1] * w.y
             + cs[4 * i + 2] * w.z + cs[4 * i + 3] * w.w;
    }
    g_proj[k * DIMS + d] = acc + b[d];
}

// ---------------- scatter out[p] = proj[label[p]] --------------------------
__global__ void scatter_kernel(float* __restrict__ out) {
    const unsigned idx = blockIdx.x * 256u + threadIdx.x;   // float4 index
    const int p = idx / (DIMS / 4), r = idx % (DIMS / 4);
    const int lb = g_labels[p];
    reinterpret_cast<float4*>(out)[idx] =
        reinterpret_cast<const float4*>(g_proj)[lb * (DIMS / 4) + r];
}

// ---------------- launch ----------------------------------------------------
extern "C" void kernel_launch(void* const* d_in, const int* in_sizes, int n_in,
                              void* d_out, int out_size) {
    const float* x = (const float*)d_in[0];
    const float* W = (const float*)d_in[1];
    const float* b = (const float*)d_in[2];
    float* out = (float*)d_out;

    cudaFuncSetAttribute(assign_kernel, cudaFuncAttributeMaxDynamicSharedMemorySize,
                         (2 * KC * 256 + 2 * KC * NK) * (int)sizeof(float));
    cudaFuncSetAttribute(accum_kernel, cudaFuncAttributeMaxDynamicSharedMemorySize,
                         2 * NK * DIMS * (int)sizeof(float));

    const int asg_smem_bytes = (2 * KC * 256 + 2 * KC * NK) * (int)sizeof(float); // 81920
    const int acc_smem_bytes = 2 * NK * DIMS * (int)sizeof(float);                // 196608

    transpose_kernel<<<dim3(DIMS / 32, NPTS / 32), dim3(32, 8)>>>(x);
    init_centers_kernel<<<NK, DIMS>>>(x);

    for (int it = 0; it < ITERS; ++it) {
        assign_kernel<<<NPTS / 256, 256, asg_smem_bytes>>>();
        accum_kernel<<<ACC_CTAS, 768, acc_smem_bytes>>>();
        update_kernel<<<NK, DIMS>>>();
    }
    assign_kernel<<<NPTS / 256, 256, asg_smem_bytes>>>();

    proj_kernel<<<NK, DIMS>>>(W, b);
    scatter_kernel<<<(NPTS * (DIMS / 4)) / 256, 256>>>(out);
}

// round 3
// speedup vs baseline: 1.0175x; 1.0175x over previous
#include <cuda_runtime.h>
#include <cstdint>

#define NPTS   65536
#define DIMS   384
#define NK     64
#define ITERS  10
#define KC     32
#define NCH    12          // DIMS / KC
#define ACC_CTAS 128
#define ACC_PTS  512       // points per accumulation CTA
#define CDS    160         // floats per dim-row of duplicated/swizzled centers

typedef unsigned long long u64;

// ---------------- scratch (device globals; no runtime allocation) ----------
__device__ float g_xt[(size_t)DIMS * NPTS];          // x transposed [D][N]
__device__ float g_centers[NK * DIMS];               // [K][D]
__device__ float g_cdup[DIMS * CDS];                 // duplicated+swizzled [D][...]
__device__ float g_cc[NK];                           // ||c_k||^2
__device__ int   g_labels[NPTS];
__device__ float g_partials[(size_t)ACC_CTAS * NK * DIMS];
__device__ float g_pcounts[ACC_CTAS * NK];
__device__ float g_proj[NK * DIMS];                  // centers @ W^T + b

// cdup layout per dim d: cluster k lives (duplicated) at
//   g_cdup[d*CDS + (k>>3)*20 + (k&7)*2 + {0,1}]
// so thread ng reads its 8 clusters as 4 conflict-free LDS.128 at ng*80 bytes.

// ---------------- PTX helpers ----------------------------------------------
__device__ __forceinline__ u64 f32x2_fma(u64 a, u64 b, u64 c) {
    u64 d;
    asm("fma.rn.f32x2 %0, %1, %2, %3;" : "=l"(d) : "l"(a), "l"(b), "l"(c));
    return d;
}
__device__ __forceinline__ void unpack2(u64 v, float& lo, float& hi) {
    unsigned a, b;
    asm("mov.b64 {%0, %1}, %2;" : "=r"(a), "=r"(b) : "l"(v));
    lo = __uint_as_float(a);
    hi = __uint_as_float(b);
}
__device__ __forceinline__ void cp16(void* smem, const void* gmem) {
    unsigned sa = (unsigned)__cvta_generic_to_shared(smem);
    asm volatile("cp.async.cg.shared.global [%0], [%1], 16;" :: "r"(sa), "l"(gmem));
}
__device__ __forceinline__ void cp_commit() {
    asm volatile("cp.async.commit_group;");
}
template <int N>
__device__ __forceinline__ void cp_wait() {
    asm volatile("cp.async.wait_group %0;" :: "n"(N));
}

// ---------------- transpose x[N][D] -> g_xt[D][N] --------------------------
__global__ void transpose_kernel(const float* __restrict__ x) {
    __shared__ float tile[32][33];
    int d0 = blockIdx.x * 32;
    int p0 = blockIdx.y * 32;
    int tx = threadIdx.x, ty = threadIdx.y;
#pragma unroll
    for (int j = 0; j < 32; j += 8)
        tile[ty + j][tx] = x[(size_t)(p0 + ty + j) * DIMS + d0 + tx];
    __syncthreads();
#pragma unroll
    for (int j = 0; j < 32; j += 8)
        g_xt[(size_t)(d0 + ty + j) * NPTS + p0 + tx] = tile[tx][ty + j];
}

// ---------------- init centers = first 64 points ---------------------------
__global__ void init_centers_kernel(const float* __restrict__ x) {
    __shared__ float red[DIMS];
    int k = blockIdx.x, d = threadIdx.x;
    float v = x[k * DIMS + d];
    g_centers[k * DIMS + d] = v;
    int off = d * CDS + (k >> 3) * 20 + (k & 7) * 2;
    g_cdup[off] = v;
    g_cdup[off + 1] = v;
    red[d] = v * v;
    __syncthreads();
    for (int s = 256; s > 0; s >>= 1) {
        if (d < s && d + s < DIMS) red[d] += red[d + s];
        __syncthreads();
    }
    if (d == 0) g_cc[k] = red[0];
}

// ---------------- assignment -----------------------------------------------
// 256 CTAs x 256 threads; CTA tile = 256 points x 64 clusters.
// Thread tile: 8 points (4 f32x2 point-pairs) x 8 clusters.
extern __shared__ float asg_smem[];

__device__ __forceinline__ void asg_prefetch(float* xs, float* cd, int buf,
                                             int kbase, unsigned pcta, int tid) {
#pragma unroll
    for (int j = 0; j < 8; ++j) {              // x tile: 2048 float4 (32KB)
        int id = j * 256 + tid;
        int r = id >> 6, c = (id & 63) << 2;
        cp16(&xs[buf * (KC * 256) + r * 256 + c],
             &g_xt[(size_t)(kbase + r) * NPTS + pcta + c]);
    }
#pragma unroll
    for (int j = 0; j < 5; ++j) {              // cdup tile: 1280 float4 (20KB)
        int id = j * 256 + tid;
        int r = id / 40, c = (id % 40) << 2;
        cp16(&cd[buf * (KC * CDS) + r * CDS + c],
             &g_cdup[(kbase + r) * CDS + c]);
    }
    cp_commit();
}

__global__ void __launch_bounds__(256, 2) assign_kernel() {
    float* xs = asg_smem;                       // [2][KC][256]
    float* cd = asg_smem + 2 * KC * 256;        // [2][KC][CDS]

    const int tid  = threadIdx.x;
    const int warp = tid >> 5, lane = tid & 31;
    const int mg = lane >> 3, ng = lane & 7;
    const int prow  = warp * 32 + mg * 8;       // first of 8 points (in tile)
    const int nbase = ng * 8;                   // first of 8 clusters
    const int ngoff = ng * 20;                  // swizzled cdup chunk (floats)
    const unsigned pcta = blockIdx.x * 256u;

    asg_prefetch(xs, cd, 0, 0, pcta, tid);

    u64 acc[4][8];
#pragma unroll
    for (int m = 0; m < 4; ++m)
#pragma unroll
        for (int n = 0; n < 8; ++n) acc[m][n] = 0ull;

    for (int kc = 0; kc < NCH; ++kc) {
        const int buf = kc & 1;
        if (kc + 1 < NCH) {
            asg_prefetch(xs, cd, buf ^ 1, (kc + 1) * KC, pcta, tid);
            cp_wait<1>();
        } else {
            cp_wait<0>();
        }
        __syncthreads();

        const float* xr = xs + buf * (KC * 256);
        const float* cr = cd + buf * (KC * CDS);
#pragma unroll 8
        for (int k = 0; k < KC; ++k) {
            // 4 point-pairs straight from aligned LDS.128 register pairs
            const ulonglong2 xp = *reinterpret_cast<const ulonglong2*>(&xr[(k << 8) + prow]);
            const ulonglong2 xq = *reinterpret_cast<const ulonglong2*>(&xr[(k << 8) + prow + 4]);
            // 8 pre-duplicated clusters, conflict-free swizzled chunks
            const ulonglong2 ca = *reinterpret_cast<const ulonglong2*>(&cr[k * CDS + ngoff]);
            const ulonglong2 cb = *reinterpret_cast<const ulonglong2*>(&cr[k * CDS + ngoff + 4]);
            const ulonglong2 cc2 = *reinterpret_cast<const ulonglong2*>(&cr[k * CDS + ngoff + 8]);
            const ulonglong2 cd2 = *reinterpret_cast<const ulonglong2*>(&cr[k * CDS + ngoff + 12]);
            const u64 xv[4] = {xp.x, xp.y, xq.x, xq.y};
            const u64 cv[8] = {ca.x, ca.y, cb.x, cb.y, cc2.x, cc2.y, cd2.x, cd2.y};
#pragma unroll
            for (int m = 0; m < 4; ++m)
#pragma unroll
                for (int n = 0; n < 8; ++n)
                    acc[m][n] = f32x2_fma(xv[m], cv[n], acc[m][n]);
        }
        __syncthreads();
    }

    // epilogue: dist = ||c||^2 - 2*dot ; argmin with lowest-index tiebreak
    float cn[8];
#pragma unroll
    for (int n = 0; n < 8; ++n) cn[n] = g_cc[nbase + n];

#pragma unroll
    for (int m = 0; m < 8; ++m) {
        float best = __int_as_float(0x7f800000);   // +inf
        int bi = NK;
#pragma unroll
        for (int n = 0; n < 8; ++n) {
            float v0, v1;
            unpack2(acc[m >> 1][n], v0, v1);
            const float dot = (m & 1) ? v1 : v0;
            const float s = fmaf(-2.0f, dot, cn[n]);
            const int idx = nbase + n;
            if (s < best || (s == best && idx < bi)) { best = s; bi = idx; }
        }
#pragma unroll
        for (int off = 1; off < 8; off <<= 1) {
            const float ob = __shfl_xor_sync(0xffffffffu, best, off);
            const int   oi = __shfl_xor_sync(0xffffffffu, bi, off);
            if (ob < best || (ob == best && oi < bi)) { best = ob; bi = oi; }
        }
        if (ng == 0) g_labels[pcta + prow + m] = bi;
    }
}

// ---------------- segment-sum accumulation ---------------------------------
// 768 threads: two 384-thread groups (copies), each with a full 64x384 smem
// sum array. Copy c handles a contiguous half of the CTA's 512 points; thread
// t owns dim t -> all smem RMWs conflict-free, fully deterministic.
// Loads hit the ORIGINAL x[N][D]: x[p*384+t] is warp-coalesced (1 wavefront).
extern __shared__ float acc_smem[];
__global__ void __launch_bounds__(768, 1) accum_kernel(const float* __restrict__ x) {
    __shared__ int   s_lb[ACC_PTS];
    __shared__ float s_cnt[2][NK];
    const int tid  = threadIdx.x;
    const int copy = (tid >= DIMS) ? 1 : 0;
    const int t    = tid - copy * DIMS;               // 0..383
    float* my = acc_smem + copy * (NK * DIMS);

    for (int i = tid; i < 2 * NK * DIMS; i += 768) acc_smem[i] = 0.f;
    const int pbase = blockIdx.x * ACC_PTS;
    if (tid < ACC_PTS) s_lb[tid] = g_labels[pbase + tid];
    __syncthreads();

    const int half = ACC_PTS / 2;                     // 256
    const float* xp = x + (size_t)(pbase + copy * half) * DIMS + t;
    const int l0 = copy * half;
    float cnt = 0.f;

    for (int j = 0; j < half; j += 8) {
        float v[8];
        int lb[8];
#pragma unroll
        for (int i = 0; i < 8; ++i) {
            v[i]  = __ldg(xp + (size_t)(j + i) * DIMS);
            lb[i] = s_lb[l0 + j + i];
        }
#pragma unroll
        for (int i = 0; i < 8; ++i) {
            my[lb[i] * DIMS + t] += v[i];
            cnt += (lb[i] == t) ? 1.f : 0.f;          // valid count for t < 64
        }
    }
    if (t < NK) s_cnt[copy][t] = cnt;
    __syncthreads();

    float* outp = g_partials + (size_t)blockIdx.x * (NK * DIMS);
    for (int i = tid; i < NK * DIMS; i += 768)
        outp[i] = acc_smem[i] + acc_smem[i + NK * DIMS];
    if (tid < NK) g_pcounts[blockIdx.x * NK + tid] = s_cnt[0][tid] + s_cnt[1][tid];
}

// ---------------- center update + ||c||^2 + duplicated centers -------------
__global__ void update_kernel() {
    __shared__ float red[DIMS];
    const int k = blockIdx.x, t = threadIdx.x;
    float sum = 0.f, cnt = 0.f;
#pragma unroll 4
    for (int c = 0; c < ACC_CTAS; ++c) {
        sum += g_partials[(size_t)c * (NK * DIMS) + k * DIMS + t];
        cnt += g_pcounts[c * NK + k];
    }
    const float v = (cnt > 0.f) ? (sum / fmaxf(cnt, 1.f)) : g_centers[k * DIMS + t];
    g_centers[k * DIMS + t] = v;
    int off = t * CDS + (k >> 3) * 20 + (k & 7) * 2;
    g_cdup[off] = v;
    g_cdup[off + 1] = v;
    red[t] = v * v;
    __syncthreads();
    for (int s = 256; s > 0; s >>= 1) {
        if (t < s && t + s < DIMS) red[t] += red[t + s];
        __syncthreads();
    }
    if (t == 0) g_cc[k] = red[0];
}

// ---------------- proj = centers @ W^T + b ---------------------------------
__global__ void proj_kernel(const float* __restrict__ W, const float* __restrict__ b) {
    __shared__ float cs[DIMS];
    const int k = blockIdx.x, d = threadIdx.x;
    cs[d] = g_centers[k * DIMS + d];
    __syncthreads();
    const float4* Wr = reinterpret_cast<const float4*>(W + (size_t)d * DIMS);
    float acc = 0.f;
#pragma unroll 4
    for (int i = 0; i < DIMS / 4; ++i) {
        const float4 w = Wr[i];
        acc += cs[4 * i] * w.x + cs[4 * i + 1] * w.y
             + cs[4 * i + 2] * w.z + cs[4 * i + 3] * w.w;
    }
    g_proj[k * DIMS + d] = acc + b[d];
}

// ---------------- scatter out[p] = proj[label[p]] --------------------------
__global__ void scatter_kernel(float* __restrict__ out) {
    const unsigned idx = blockIdx.x * 256u + threadIdx.x;   // float4 index
    const int p = idx / (DIMS / 4), r = idx % (DIMS / 4);
    const int lb = g_labels[p];
    reinterpret_cast<float4*>(out)[idx] =
        reinterpret_cast<const float4*>(g_proj)[lb * (DIMS / 4) + r];
}

// ---------------- launch ----------------------------------------------------
extern "C" void kernel_launch(void* const* d_in, const int* in_sizes, int n_in,
                              void* d_out, int out_size) {
    const float* x = (const float*)d_in[0];
    const float* W = (const float*)d_in[1];
    const float* b = (const float*)d_in[2];
    float* out = (float*)d_out;

    const int asg_smem_bytes = (2 * KC * 256 + 2 * KC * CDS) * (int)sizeof(float); // 106496
    const int acc_smem_bytes = 2 * NK * DIMS * (int)sizeof(float);                 // 196608

    cudaFuncSetAttribute(assign_kernel, cudaFuncAttributeMaxDynamicSharedMemorySize,
                         asg_smem_bytes);
    cudaFuncSetAttribute(accum_kernel, cudaFuncAttributeMaxDynamicSharedMemorySize,
                         acc_smem_bytes);

    transpose_kernel<<<dim3(DIMS / 32, NPTS / 32), dim3(32, 8)>>>(x);
    init_centers_kernel<<<NK, DIMS>>>(x);

    for (int it = 0; it < ITERS; ++it) {
        assign_kernel<<<NPTS / 256, 256, asg_smem_bytes>>>();
        accum_kernel<<<ACC_CTAS, 768, acc_smem_bytes>>>(x);
        update_kernel<<<NK, DIMS>>>();
    }
    assign_kernel<<<NPTS / 256, 256, asg_smem_bytes>>>();

    proj_kernel<<<NK, DIMS>>>(W, b);
    scatter_kernel<<<(NPTS * (DIMS / 4)) / 256, 256>>>(out);
}

// round 4
// speedup vs baseline: 1.0278x; 1.0101x over previous
#include <cuda_runtime.h>
#include <cstdint>

#define NPTS   65536
#define DIMS   384
#define NK     64
#define ITERS  10
#define KC     32
#define NCH    12          // DIMS / KC
#define ACC_CTAS 256
#define ACC_PTS  256       // points per accumulation CTA
#define CDS    160         // floats per dim-row of duplicated/swizzled centers

typedef unsigned long long u64;

// ---------------- scratch (device globals; no runtime allocation) ----------
__device__ float g_xt[(size_t)DIMS * NPTS];          // x transposed [D][N]
__device__ float g_centers[NK * DIMS];               // [K][D]
__device__ float g_cdup[DIMS * CDS];                 // duplicated+swizzled [D][...]
__device__ float g_cc[NK];                           // ||c_k||^2
__device__ int   g_labels[NPTS];
__device__ float g_partials[(size_t)ACC_CTAS * NK * DIMS];   // 25.2 MB
__device__ float g_pcounts[NK * ACC_CTAS];           // transposed: [k][c]
__device__ float g_proj[NK * DIMS];                  // centers @ W^T + b

// cdup layout per dim d: cluster k lives (duplicated) at
//   g_cdup[d*CDS + (k>>3)*20 + (k&7)*2 + {0,1}]
// so thread ng reads its 8 clusters as 4 conflict-free LDS.128 at ng*80 bytes.

// ---------------- PTX helpers ----------------------------------------------
__device__ __forceinline__ u64 f32x2_fma(u64 a, u64 b, u64 c) {
    u64 d;
    asm("fma.rn.f32x2 %0, %1, %2, %3;" : "=l"(d) : "l"(a), "l"(b), "l"(c));
    return d;
}
__device__ __forceinline__ void unpack2(u64 v, float& lo, float& hi) {
    unsigned a, b;
    asm("mov.b64 {%0, %1}, %2;" : "=r"(a), "=r"(b) : "l"(v));
    lo = __uint_as_float(a);
    hi = __uint_as_float(b);
}
__device__ __forceinline__ void cp16(void* smem, const void* gmem) {
    unsigned sa = (unsigned)__cvta_generic_to_shared(smem);
    asm volatile("cp.async.cg.shared.global [%0], [%1], 16;" :: "r"(sa), "l"(gmem));
}
__device__ __forceinline__ void cp_commit() {
    asm volatile("cp.async.commit_group;");
}
template <int N>
__device__ __forceinline__ void cp_wait() {
    asm volatile("cp.async.wait_group %0;" :: "n"(N));
}

// ---------------- transpose x[N][D] -> g_xt[D][N] --------------------------
__global__ void transpose_kernel(const float* __restrict__ x) {
    __shared__ float tile[32][33];
    int d0 = blockIdx.x * 32;
    int p0 = blockIdx.y * 32;
    int tx = threadIdx.x, ty = threadIdx.y;
#pragma unroll
    for (int j = 0; j < 32; j += 8)
        tile[ty + j][tx] = x[(size_t)(p0 + ty + j) * DIMS + d0 + tx];
    __syncthreads();
#pragma unroll
    for (int j = 0; j < 32; j += 8)
        g_xt[(size_t)(d0 + ty + j) * NPTS + p0 + tx] = tile[tx][ty + j];
}

// ---------------- init centers = first 64 points ---------------------------
__global__ void init_centers_kernel(const float* __restrict__ x) {
    __shared__ float red[DIMS];
    int k = blockIdx.x, d = threadIdx.x;
    float v = x[k * DIMS + d];
    g_centers[k * DIMS + d] = v;
    int off = d * CDS + (k >> 3) * 20 + (k & 7) * 2;
    g_cdup[off] = v;
    g_cdup[off + 1] = v;
    red[d] = v * v;
    __syncthreads();
    for (int s = 256; s > 0; s >>= 1) {
        if (d < s && d + s < DIMS) red[d] += red[d + s];
        __syncthreads();
    }
    if (d == 0) g_cc[k] = red[0];
}

// ---------------- assignment -----------------------------------------------
// 256 CTAs x 256 threads; CTA tile = 256 points x 64 clusters.
// Thread tile: 8 points (4 f32x2 point-pairs) x 8 clusters.
extern __shared__ float asg_smem[];

__device__ __forceinline__ void asg_prefetch(float* xs, float* cd, int buf,
                                             int kbase, unsigned pcta, int tid) {
#pragma unroll
    for (int j = 0; j < 8; ++j) {              // x tile: 2048 float4 (32KB)
        int id = j * 256 + tid;
        int r = id >> 6, c = (id & 63) << 2;
        cp16(&xs[buf * (KC * 256) + r * 256 + c],
             &g_xt[(size_t)(kbase + r) * NPTS + pcta + c]);
    }
#pragma unroll
    for (int j = 0; j < 5; ++j) {              // cdup tile: 1280 float4 (20KB)
        int id = j * 256 + tid;
        int r = id / 40, c = (id % 40) << 2;
        cp16(&cd[buf * (KC * CDS) + r * CDS + c],
             &g_cdup[(kbase + r) * CDS + c]);
    }
    cp_commit();
}

__global__ void __launch_bounds__(256, 2) assign_kernel() {
    float* xs = asg_smem;                       // [2][KC][256]
    float* cd = asg_smem + 2 * KC * 256;        // [2][KC][CDS]

    const int tid  = threadIdx.x;
    const int warp = tid >> 5, lane = tid & 31;
    const int mg = lane >> 3, ng = lane & 7;
    const int prow  = warp * 32 + mg * 8;       // first of 8 points (in tile)
    const int nbase = ng * 8;                   // first of 8 clusters
    const int ngoff = ng * 20;                  // swizzled cdup chunk (floats)
    const unsigned pcta = blockIdx.x * 256u;

    asg_prefetch(xs, cd, 0, 0, pcta, tid);

    u64 acc[4][8];
#pragma unroll
    for (int m = 0; m < 4; ++m)
#pragma unroll
        for (int n = 0; n < 8; ++n) acc[m][n] = 0ull;

    for (int kc = 0; kc < NCH; ++kc) {
        const int buf = kc & 1;
        if (kc + 1 < NCH) {
            asg_prefetch(xs, cd, buf ^ 1, (kc + 1) * KC, pcta, tid);
            cp_wait<1>();
        } else {
            cp_wait<0>();
        }
        __syncthreads();

        const float* xr = xs + buf * (KC * 256);
        const float* cr = cd + buf * (KC * CDS);
#pragma unroll 8
        for (int k = 0; k < KC; ++k) {
            const ulonglong2 xp = *reinterpret_cast<const ulonglong2*>(&xr[(k << 8) + prow]);
            const ulonglong2 xq = *reinterpret_cast<const ulonglong2*>(&xr[(k << 8) + prow + 4]);
            const ulonglong2 ca = *reinterpret_cast<const ulonglong2*>(&cr[k * CDS + ngoff]);
            const ulonglong2 cb = *reinterpret_cast<const ulonglong2*>(&cr[k * CDS + ngoff + 4]);
            const ulonglong2 cc2 = *reinterpret_cast<const ulonglong2*>(&cr[k * CDS + ngoff + 8]);
            const ulonglong2 cd2 = *reinterpret_cast<const ulonglong2*>(&cr[k * CDS + ngoff + 12]);
            const u64 xv[4] = {xp.x, xp.y, xq.x, xq.y};
            const u64 cv[8] = {ca.x, ca.y, cb.x, cb.y, cc2.x, cc2.y, cd2.x, cd2.y};
#pragma unroll
            for (int m = 0; m < 4; ++m)
#pragma unroll
                for (int n = 0; n < 8; ++n)
                    acc[m][n] = f32x2_fma(xv[m], cv[n], acc[m][n]);
        }
        __syncthreads();
    }

    // epilogue: dist = ||c||^2 - 2*dot ; argmin with lowest-index tiebreak
    float cn[8];
#pragma unroll
    for (int n = 0; n < 8; ++n) cn[n] = g_cc[nbase + n];

#pragma unroll
    for (int m = 0; m < 8; ++m) {
        float best = __int_as_float(0x7f800000);   // +inf
        int bi = NK;
#pragma unroll
        for (int n = 0; n < 8; ++n) {
            float v0, v1;
            unpack2(acc[m >> 1][n], v0, v1);
            const float dot = (m & 1) ? v1 : v0;
            const float s = fmaf(-2.0f, dot, cn[n]);
            const int idx = nbase + n;
            if (s < best || (s == best && idx < bi)) { best = s; bi = idx; }
        }
#pragma unroll
        for (int off = 1; off < 8; off <<= 1) {
            const float ob = __shfl_xor_sync(0xffffffffu, best, off);
            const int   oi = __shfl_xor_sync(0xffffffffu, bi, off);
            if (ob < best || (ob == best && oi < bi)) { best = ob; bi = oi; }
        }
        if (ng == 0) g_labels[pcta + prow + m] = bi;
    }
}

// ---------------- segment-sum accumulation ---------------------------------
// 256 CTAs x 384 threads; thread t owns dim t -> all smem RMWs conflict-free
// and deterministic. Loads from original x[N][D] are warp-coalesced; unroll 16
// for deep MLP (DRAM-latency hiding).
extern __shared__ float acc_smem[];
__global__ void __launch_bounds__(384, 2) accum_kernel(const float* __restrict__ x) {
    __shared__ int s_lb[ACC_PTS];
    const int t = threadIdx.x;

    for (int i = t; i < NK * DIMS; i += 384) acc_smem[i] = 0.f;
    const int pbase = blockIdx.x * ACC_PTS;
    if (t < ACC_PTS) s_lb[t] = g_labels[pbase + t];
    __syncthreads();

    const float* xp = x + (size_t)pbase * DIMS + t;
    float cnt = 0.f;

    for (int j = 0; j < ACC_PTS; j += 16) {
        float v[16];
        int lb[16];
#pragma unroll
        for (int i = 0; i < 16; ++i) {
            v[i]  = __ldg(xp + (size_t)(j + i) * DIMS);
            lb[i] = s_lb[j + i];
        }
#pragma unroll
        for (int i = 0; i < 16; ++i) {
            acc_smem[lb[i] * DIMS + t] += v[i];
            cnt += (lb[i] == t) ? 1.f : 0.f;          // valid count for t < 64
        }
    }
    __syncthreads();

    float* outp = g_partials + (size_t)blockIdx.x * (NK * DIMS);
    for (int i = t; i < NK * DIMS; i += 384) outp[i] = acc_smem[i];
    if (t < NK) g_pcounts[t * ACC_CTAS + blockIdx.x] = cnt;   // transposed
}

// ---------------- center update + ||c||^2 + duplicated centers -------------
// CTA = cluster k; thread t owns dim t. Counts pre-reduced from the transposed
// g_pcounts (exact integers -> order-free). Partial sum unrolled 16 for MLP.
__global__ void __launch_bounds__(DIMS, 1) update_kernel() {
    __shared__ float red[DIMS];
    __shared__ float s_c[NK];
    __shared__ float s_cnt;
    const int k = blockIdx.x, t = threadIdx.x;

    if (t < NK) {
        const float4 a = *reinterpret_cast<const float4*>(&g_pcounts[k * ACC_CTAS + t * 4]);
        s_c[t] = a.x + a.y + a.z + a.w;
    }

    float sum = 0.f;
    const float* pp = g_partials + k * DIMS + t;
    for (int c = 0; c < ACC_CTAS; c += 16) {
#pragma unroll
        for (int i = 0; i < 16; ++i)
            sum += __ldg(pp + (size_t)(c + i) * (NK * DIMS));
    }

    __syncthreads();
    if (t == 0) {
        float s = 0.f;
#pragma unroll
        for (int i = 0; i < NK; ++i) s += s_c[i];
        s_cnt = s;
    }
    __syncthreads();

    const float cnt = s_cnt;
    const float v = (cnt > 0.f) ? (sum / fmaxf(cnt, 1.f)) : g_centers[k * DIMS + t];
    g_centers[k * DIMS + t] = v;
    const int off = t * CDS + (k >> 3) * 20 + (k & 7) * 2;
    g_cdup[off] = v;
    g_cdup[off + 1] = v;
    red[t] = v * v;
    __syncthreads();
    for (int s = 256; s > 0; s >>= 1) {
        if (t < s && t + s < DIMS) red[t] += red[t + s];
        __syncthreads();
    }
    if (t == 0) g_cc[k] = red[0];
}

// ---------------- proj = centers @ W^T + b ---------------------------------
__global__ void proj_kernel(const float* __restrict__ W, const float* __restrict__ b) {
    __shared__ float cs[DIMS];
    const int k = blockIdx.x, d = threadIdx.x;
    cs[d] = g_centers[k * DIMS + d];
    __syncthreads();
    const float4* Wr = reinterpret_cast<const float4*>(W + (size_t)d * DIMS);
    float acc = 0.f;
#pragma unroll 4
    for (int i = 0; i < DIMS / 4; ++i) {
        const float4 w = Wr[i];
        acc += cs[4 * i] * w.x + cs[4 * i + 1] * w.y
             + cs[4 * i + 2] * w.z + cs[4 * i + 3] * w.w;
    }
    g_proj[k * DIMS + d] = acc + b[d];
}

// ---------------- scatter out[p] = proj[label[p]] --------------------------
__global__ void scatter_kernel(float* __restrict__ out) {
    const unsigned idx = blockIdx.x * 256u + threadIdx.x;   // float4 index
    const int p = idx / (DIMS / 4), r = idx % (DIMS / 4);
    const int lb = g_labels[p];
    reinterpret_cast<float4*>(out)[idx] =
        reinterpret_cast<const float4*>(g_proj)[lb * (DIMS / 4) + r];
}

// ---------------- launch ----------------------------------------------------
extern "C" void kernel_launch(void* const* d_in, const int* in_sizes, int n_in,
                              void* d_out, int out_size) {
    const float* x = (const float*)d_in[0];
    const float* W = (const float*)d_in[1];
    const float* b = (const float*)d_in[2];
    float* out = (float*)d_out;

    const int asg_smem_bytes = (2 * KC * 256 + 2 * KC * CDS) * (int)sizeof(float); // 106496
    const int acc_smem_bytes = NK * DIMS * (int)sizeof(float);                      // 98304

    cudaFuncSetAttribute(assign_kernel, cudaFuncAttributeMaxDynamicSharedMemorySize,
                         asg_smem_bytes);
    cudaFuncSetAttribute(accum_kernel, cudaFuncAttributeMaxDynamicSharedMemorySize,
                         acc_smem_bytes);

    transpose_kernel<<<dim3(DIMS / 32, NPTS / 32), dim3(32, 8)>>>(x);
    init_centers_kernel<<<NK, DIMS>>>(x);

    for (int it = 0; it < ITERS; ++it) {
        assign_kernel<<<NPTS / 256, 256, asg_smem_bytes>>>();
        accum_kernel<<<ACC_CTAS, 384, acc_smem_bytes>>>(x);
        update_kernel<<<NK, DIMS>>>();
    }
    assign_kernel<<<NPTS / 256, 256, asg_smem_bytes>>>();

    proj_kernel<<<NK, DIMS>>>(W, b);
    scatter_kernel<<<(NPTS * (DIMS / 4)) / 256, 256>>>(out);
}

// round 5
// speedup vs baseline: 1.0357x; 1.0078x over previous
#include <cuda_runtime.h>
#include <cstdint>

#define NPTS   65536
#define DIMS   384
#define NK     64
#define ITERS  10
#define KC     32
#define NCH    12          // DIMS / KC
#define ACC_CTAS 256
#define ACC_PTS  256       // points per accumulation CTA
#define CDS    160         // floats per dim-row of duplicated/swizzled centers

typedef unsigned long long u64;

// ---------------- scratch (device globals; no runtime allocation) ----------
__device__ float g_xt[(size_t)DIMS * NPTS];          // x transposed [D][N]
__device__ float g_centers[NK * DIMS];               // [K][D]
__device__ float g_cdup[DIMS * CDS];                 // duplicated+swizzled [D][...]
__device__ float g_cc[NK];                           // ||c_k||^2
__device__ int   g_labels[NPTS];
__device__ float g_partials[(size_t)ACC_CTAS * NK * DIMS];   // 25.2 MB
__device__ float g_pcounts[NK * ACC_CTAS];           // transposed: [k][c]
__device__ float g_csum[NK * DIMS];                  // reduced partials
__device__ float g_proj[NK * DIMS];                  // centers @ W^T + b

// cdup layout per dim d: cluster k lives (duplicated) at
//   g_cdup[d*CDS + (k>>3)*20 + (k&7)*2 + {0,1}]
// so thread ng reads its 8 clusters as 4 conflict-free LDS.128 at ng*80 bytes.

// ---------------- PTX helpers ----------------------------------------------
__device__ __forceinline__ u64 f32x2_fma(u64 a, u64 b, u64 c) {
    u64 d;
    asm("fma.rn.f32x2 %0, %1, %2, %3;" : "=l"(d) : "l"(a), "l"(b), "l"(c));
    return d;
}
__device__ __forceinline__ void unpack2(u64 v, float& lo, float& hi) {
    unsigned a, b;
    asm("mov.b64 {%0, %1}, %2;" : "=r"(a), "=r"(b) : "l"(v));
    lo = __uint_as_float(a);
    hi = __uint_as_float(b);
}
__device__ __forceinline__ void cp16(void* smem, const void* gmem) {
    unsigned sa = (unsigned)__cvta_generic_to_shared(smem);
    asm volatile("cp.async.cg.shared.global [%0], [%1], 16;" :: "r"(sa), "l"(gmem));
}
__device__ __forceinline__ void cp_commit() {
    asm volatile("cp.async.commit_group;");
}
template <int N>
__device__ __forceinline__ void cp_wait() {
    asm volatile("cp.async.wait_group %0;" :: "n"(N));
}

// ---------------- transpose x[N][D] -> g_xt[D][N] --------------------------
__global__ void transpose_kernel(const float* __restrict__ x) {
    __shared__ float tile[32][33];
    int d0 = blockIdx.x * 32;
    int p0 = blockIdx.y * 32;
    int tx = threadIdx.x, ty = threadIdx.y;
#pragma unroll
    for (int j = 0; j < 32; j += 8)
        tile[ty + j][tx] = x[(size_t)(p0 + ty + j) * DIMS + d0 + tx];
    __syncthreads();
#pragma unroll
    for (int j = 0; j < 32; j += 8)
        g_xt[(size_t)(d0 + ty + j) * NPTS + p0 + tx] = tile[tx][ty + j];
}

// ---------------- init centers = first 64 points ---------------------------
__global__ void init_centers_kernel(const float* __restrict__ x) {
    __shared__ float red[DIMS];
    int k = blockIdx.x, d = threadIdx.x;
    float v = x[k * DIMS + d];
    g_centers[k * DIMS + d] = v;
    int off = d * CDS + (k >> 3) * 20 + (k & 7) * 2;
    g_cdup[off] = v;
    g_cdup[off + 1] = v;
    red[d] = v * v;
    __syncthreads();
    for (int s = 256; s > 0; s >>= 1) {
        if (d < s && d + s < DIMS) red[d] += red[d + s];
        __syncthreads();
    }
    if (d == 0) g_cc[k] = red[0];
}

// ---------------- assignment -----------------------------------------------
// 256 CTAs x 256 threads; CTA tile = 256 points x 64 clusters.
// Thread tile: 8 points (4 f32x2 point-pairs) x 8 clusters.
extern __shared__ float asg_smem[];

__device__ __forceinline__ void asg_prefetch(float* xs, float* cd, int buf,
                                             int kbase, unsigned pcta, int tid) {
#pragma unroll
    for (int j = 0; j < 8; ++j) {              // x tile: 2048 float4 (32KB)
        int id = j * 256 + tid;
        int r = id >> 6, c = (id & 63) << 2;
        cp16(&xs[buf * (KC * 256) + r * 256 + c],
             &g_xt[(size_t)(kbase + r) * NPTS + pcta + c]);
    }
#pragma unroll
    for (int j = 0; j < 5; ++j) {              // cdup tile: 1280 float4 (20KB)
        int id = j * 256 + tid;
        int r = id / 40, c = (id % 40) << 2;
        cp16(&cd[buf * (KC * CDS) + r * CDS + c],
             &g_cdup[(kbase + r) * CDS + c]);
    }
    cp_commit();
}

__global__ void __launch_bounds__(256, 2) assign_kernel() {
    float* xs = asg_smem;                       // [2][KC][256]
    float* cd = asg_smem + 2 * KC * 256;        // [2][KC][CDS]

    const int tid  = threadIdx.x;
    const int warp = tid >> 5, lane = tid & 31;
    const int mg = lane >> 3, ng = lane & 7;
    const int prow  = warp * 32 + mg * 8;       // first of 8 points (in tile)
    const int nbase = ng * 8;                   // first of 8 clusters
    const int ngoff = ng * 20;                  // swizzled cdup chunk (floats)
    const unsigned pcta = blockIdx.x * 256u;

    asg_prefetch(xs, cd, 0, 0, pcta, tid);

    u64 acc[4][8];
#pragma unroll
    for (int m = 0; m < 4; ++m)
#pragma unroll
        for (int n = 0; n < 8; ++n) acc[m][n] = 0ull;

    for (int kc = 0; kc < NCH; ++kc) {
        const int buf = kc & 1;
        if (kc + 1 < NCH) {
            asg_prefetch(xs, cd, buf ^ 1, (kc + 1) * KC, pcta, tid);
            cp_wait<1>();
        } else {
            cp_wait<0>();
        }
        __syncthreads();

        const float* xr = xs + buf * (KC * 256);
        const float* cr = cd + buf * (KC * CDS);
#pragma unroll 8
        for (int k = 0; k < KC; ++k) {
            const ulonglong2 xp = *reinterpret_cast<const ulonglong2*>(&xr[(k << 8) + prow]);
            const ulonglong2 xq = *reinterpret_cast<const ulonglong2*>(&xr[(k << 8) + prow + 4]);
            const ulonglong2 ca = *reinterpret_cast<const ulonglong2*>(&cr[k * CDS + ngoff]);
            const ulonglong2 cb = *reinterpret_cast<const ulonglong2*>(&cr[k * CDS + ngoff + 4]);
            const ulonglong2 cc2 = *reinterpret_cast<const ulonglong2*>(&cr[k * CDS + ngoff + 8]);
            const ulonglong2 cd2 = *reinterpret_cast<const ulonglong2*>(&cr[k * CDS + ngoff + 12]);
            const u64 xv[4] = {xp.x, xp.y, xq.x, xq.y};
            const u64 cv[8] = {ca.x, ca.y, cb.x, cb.y, cc2.x, cc2.y, cd2.x, cd2.y};
#pragma unroll
            for (int m = 0; m < 4; ++m)
#pragma unroll
                for (int n = 0; n < 8; ++n)
                    acc[m][n] = f32x2_fma(xv[m], cv[n], acc[m][n]);
        }
        __syncthreads();
    }

    // epilogue: dist = ||c||^2 - 2*dot ; argmin with lowest-index tiebreak
    float cn[8];
#pragma unroll
    for (int n = 0; n < 8; ++n) cn[n] = g_cc[nbase + n];

#pragma unroll
    for (int m = 0; m < 8; ++m) {
        float best = __int_as_float(0x7f800000);   // +inf
        int bi = NK;
#pragma unroll
        for (int n = 0; n < 8; ++n) {
            float v0, v1;
            unpack2(acc[m >> 1][n], v0, v1);
            const float dot = (m & 1) ? v1 : v0;
            const float s = fmaf(-2.0f, dot, cn[n]);
            const int idx = nbase + n;
            if (s < best || (s == best && idx < bi)) { best = s; bi = idx; }
        }
#pragma unroll
        for (int off = 1; off < 8; off <<= 1) {
            const float ob = __shfl_xor_sync(0xffffffffu, best, off);
            const int   oi = __shfl_xor_sync(0xffffffffu, bi, off);
            if (ob < best || (ob == best && oi < bi)) { best = ob; bi = oi; }
        }
        if (ng == 0) g_labels[pcta + prow + m] = bi;
    }
}

// ---------------- segment-sum accumulation ---------------------------------
// 256 CTAs x 384 threads; thread t owns dim t -> all smem RMWs conflict-free
// and deterministic. Loads from original x[N][D] are warp-coalesced; one long
// 32-deep LDG burst per batch for DRAM latency hiding.
extern __shared__ float acc_smem[];
__global__ void __launch_bounds__(384, 2) accum_kernel(const float* __restrict__ x) {
    __shared__ int s_lb[ACC_PTS];
    const int t = threadIdx.x;

    for (int i = t; i < NK * DIMS; i += 384) acc_smem[i] = 0.f;
    const int pbase = blockIdx.x * ACC_PTS;
    if (t < ACC_PTS) s_lb[t] = g_labels[pbase + t];
    __syncthreads();

    const float* xp = x + (size_t)pbase * DIMS + t;
    float cnt = 0.f;

    for (int j = 0; j < ACC_PTS; j += 32) {
        float v[32];
#pragma unroll
        for (int i = 0; i < 32; ++i)
            v[i] = __ldg(xp + (unsigned)(j + i) * DIMS);
        int lb[32];
#pragma unroll
        for (int i = 0; i < 32; ++i)
            lb[i] = s_lb[j + i];
#pragma unroll
        for (int i = 0; i < 32; ++i) {
            acc_smem[lb[i] * DIMS + t] += v[i];
            cnt += (lb[i] == t) ? 1.f : 0.f;          // valid count for t < 64
        }
    }
    __syncthreads();

    float* outp = g_partials + (size_t)blockIdx.x * (NK * DIMS);
    for (int i = t; i < NK * DIMS; i += 384) outp[i] = acc_smem[i];
    if (t < NK) g_pcounts[t * ACC_CTAS + blockIdx.x] = cnt;   // transposed
}

// ---------------- partials reduction: 192 CTAs, full-chip ------------------
// Element e = (k,d); sums 256 partials in ascending order (bitwise identical
// to the previous in-update reduction). Coalesced: warp spans consecutive d.
__global__ void __launch_bounds__(128, 8) reduce_kernel() {
    const int e = blockIdx.x * 128 + threadIdx.x;     // 0 .. 24575
    const float* pp = g_partials + e;
    float sum = 0.f;
    for (int c = 0; c < ACC_CTAS; c += 16) {
#pragma unroll
        for (int i = 0; i < 16; ++i)
            sum += __ldg(pp + (size_t)(c + i) * (NK * DIMS));
    }
    g_csum[e] = sum;
}

// ---------------- center update + ||c||^2 + duplicated centers -------------
__global__ void __launch_bounds__(DIMS, 1) update_kernel() {
    __shared__ float red[DIMS];
    __shared__ float s_c[NK];
    __shared__ float s_cnt;
    const int k = blockIdx.x, t = threadIdx.x;

    if (t < NK) {
        const float4 a = *reinterpret_cast<const float4*>(&g_pcounts[k * ACC_CTAS + t * 4]);
        s_c[t] = a.x + a.y + a.z + a.w;
    }
    const float sum = g_csum[k * DIMS + t];

    __syncthreads();
    if (t == 0) {
        float s = 0.f;
#pragma unroll
        for (int i = 0; i < NK; ++i) s += s_c[i];
        s_cnt = s;
    }
    __syncthreads();

    const float cnt = s_cnt;
    const float v = (cnt > 0.f) ? (sum / fmaxf(cnt, 1.f)) : g_centers[k * DIMS + t];
    g_centers[k * DIMS + t] = v;
    const int off = t * CDS + (k >> 3) * 20 + (k & 7) * 2;
    g_cdup[off] = v;
    g_cdup[off + 1] = v;
    red[t] = v * v;
    __syncthreads();
    for (int s = 256; s > 0; s >>= 1) {
        if (t < s && t + s < DIMS) red[t] += red[t + s];
        __syncthreads();
    }
    if (t == 0) g_cc[k] = red[0];
}

// ---------------- proj = centers @ W^T + b ---------------------------------
__global__ void proj_kernel(const float* __restrict__ W, const float* __restrict__ b) {
    __shared__ float cs[DIMS];
    const int k = blockIdx.x, d = threadIdx.x;
    cs[d] = g_centers[k * DIMS + d];
    __syncthreads();
    const float4* Wr = reinterpret_cast<const float4*>(W + (size_t)d * DIMS);
    float acc = 0.f;
#pragma unroll 4
    for (int i = 0; i < DIMS / 4; ++i) {
        const float4 w = Wr[i];
        acc += cs[4 * i] * w.x + cs[4 * i + 1] * w.y
             + cs[4 * i + 2] * w.z + cs[4 * i + 3] * w.w;
    }
    g_proj[k * DIMS + d] = acc + b[d];
}

// ---------------- scatter out[p] = proj[label[p]] --------------------------
__global__ void scatter_kernel(float* __restrict__ out) {
    const unsigned idx = blockIdx.x * 256u + threadIdx.x;   // float4 index
    const int p = idx / (DIMS / 4), r = idx % (DIMS / 4);
    const int lb = g_labels[p];
    reinterpret_cast<float4*>(out)[idx] =
        reinterpret_cast<const float4*>(g_proj)[lb * (DIMS / 4) + r];
}

// ---------------- launch ----------------------------------------------------
extern "C" void kernel_launch(void* const* d_in, const int* in_sizes, int n_in,
                              void* d_out, int out_size) {
    const float* x = (const float*)d_in[0];
    const float* W = (const float*)d_in[1];
    const float* b = (const float*)d_in[2];
    float* out = (float*)d_out;

    const int asg_smem_bytes = (2 * KC * 256 + 2 * KC * CDS) * (int)sizeof(float); // 106496
    const int acc_smem_bytes = NK * DIMS * (int)sizeof(float);                      // 98304

    cudaFuncSetAttribute(assign_kernel, cudaFuncAttributeMaxDynamicSharedMemorySize,
                         asg_smem_bytes);
    cudaFuncSetAttribute(accum_kernel, cudaFuncAttributeMaxDynamicSharedMemorySize,
                         acc_smem_bytes);

    transpose_kernel<<<dim3(DIMS / 32, NPTS / 32), dim3(32, 8)>>>(x);
    init_centers_kernel<<<NK, DIMS>>>(x);

    for (int it = 0; it < ITERS; ++it) {
        assign_kernel<<<NPTS / 256, 256, asg_smem_bytes>>>();
        accum_kernel<<<ACC_CTAS, 384, acc_smem_bytes>>>(x);
        reduce_kernel<<<(NK * DIMS) / 128, 128>>>();
        update_kernel<<<NK, DIMS>>>();
    }
    assign_kernel<<<NPTS / 256, 256, asg_smem_bytes>>>();

    proj_kernel<<<NK, DIMS>>>(W, b);
    scatter_kernel<<<(NPTS * (DIMS / 4)) / 256, 256>>>(out);
}

// round 7
// speedup vs baseline: 1.0682x; 1.0313x over previous
#include <cuda_runtime.h>
#include <cstdint>

#define NPTS   65536
#define DIMS   384
#define NK     64
#define ITERS  10
#define KC     32
#define NCH    12          // DIMS / KC
#define ACC_CTAS 256
#define ACC_PTS  256       // points per accumulation CTA
#define CDS    96          // padded row: group ng at offset ng*12 (16B-aligned, bank-perfect)

typedef unsigned long long u64;

// ---------------- scratch (device globals; no runtime allocation) ----------
__device__ float g_xt[(size_t)DIMS * NPTS];          // x transposed [D][N]
__device__ float g_centers[NK * DIMS];               // [K][D]
__device__ float g_cpad[DIMS * CDS];                 // padded centers [D][96]
__device__ float g_cc[NK];                           // ||c_k||^2
__device__ int   g_labels[NPTS];
__device__ float g_partials[(size_t)ACC_CTAS * NK * DIMS];   // 25.2 MB
__device__ float g_pcounts[NK * ACC_CTAS];           // [k][c]
__device__ float g_proj[NK * DIMS];                  // centers @ W^T + b

// cpad layout per dim d: cluster k at g_cpad[d*CDS + (k>>3)*12 + (k&7)].
// Thread ng reads its 8 clusters as 2 LDS.128 at float offset ng*12 (48B:
// 16B-aligned). Banks ng*12 mod 32 = {0,12,24,4,16,28,8,20} -> conflict-free.

// ---------------- PTX helpers ----------------------------------------------
__device__ __forceinline__ u64 f32x2_fma(u64 a, u64 b, u64 c) {
    u64 d;
    asm("fma.rn.f32x2 %0, %1, %2, %3;" : "=l"(d) : "l"(a), "l"(b), "l"(c));
    return d;
}
__device__ __forceinline__ u64 dup2(float f) {
    unsigned u = __float_as_uint(f);
    u64 r;
    asm("mov.b64 %0, {%1, %1};" : "=l"(r) : "r"(u));
    return r;
}
__device__ __forceinline__ void unpack2(u64 v, float& lo, float& hi) {
    unsigned a, b;
    asm("mov.b64 {%0, %1}, %2;" : "=r"(a), "=r"(b) : "l"(v));
    lo = __uint_as_float(a);
    hi = __uint_as_float(b);
}
__device__ __forceinline__ void cp16(void* smem, const void* gmem) {
    unsigned sa = (unsigned)__cvta_generic_to_shared(smem);
    asm volatile("cp.async.cg.shared.global [%0], [%1], 16;" :: "r"(sa), "l"(gmem));
}
__device__ __forceinline__ void cp_commit() {
    asm volatile("cp.async.commit_group;");
}
template <int N>
__device__ __forceinline__ void cp_wait() {
    asm volatile("cp.async.wait_group %0;" :: "n"(N));
}

// ---------------- transpose x[N][D] -> g_xt[D][N] --------------------------
__global__ void transpose_kernel(const float* __restrict__ x) {
    __shared__ float tile[32][33];
    int d0 = blockIdx.x * 32;
    int p0 = blockIdx.y * 32;
    int tx = threadIdx.x, ty = threadIdx.y;
#pragma unroll
    for (int j = 0; j < 32; j += 8)
        tile[ty + j][tx] = x[(size_t)(p0 + ty + j) * DIMS + d0 + tx];
    __syncthreads();
#pragma unroll
    for (int j = 0; j < 32; j += 8)
        g_xt[(size_t)(d0 + ty + j) * NPTS + p0 + tx] = tile[tx][ty + j];
}

// ---------------- init centers = first 64 points ---------------------------
__global__ void init_centers_kernel(const float* __restrict__ x) {
    __shared__ float red[DIMS];
    int k = blockIdx.x, d = threadIdx.x;
    float v = x[k * DIMS + d];
    g_centers[k * DIMS + d] = v;
    g_cpad[d * CDS + (k >> 3) * 12 + (k & 7)] = v;
    red[d] = v * v;
    __syncthreads();
    for (int s = 256; s > 0; s >>= 1) {
        if (d < s && d + s < DIMS) red[d] += red[d + s];
        __syncthreads();
    }
    if (d == 0) g_cc[k] = red[0];
}

// ---------------- assignment -----------------------------------------------
// 256 CTAs x 256 threads; CTA tile = 256 points x 64 clusters.
// Thread tile: 8 points (4 f32x2 point-pairs) x 8 clusters.
// Per k: 2 LDS.128 (x) + 2 LDS.128 (centers) + 8 dup movs + 32 FFMA2.
extern __shared__ float asg_smem[];

__device__ __forceinline__ void asg_prefetch(float* xs, float* cd, int buf,
                                             int kbase, unsigned pcta, int tid) {
#pragma unroll
    for (int j = 0; j < 8; ++j) {              // x tile: 2048 float4 (32KB)
        int id = j * 256 + tid;
        int r = id >> 6, c = (id & 63) << 2;
        cp16(&xs[buf * (KC * 256) + r * 256 + c],
             &g_xt[(size_t)(kbase + r) * NPTS + pcta + c]);
    }
#pragma unroll
    for (int j = 0; j < 3; ++j) {              // centers tile: 768 float4 (12KB)
        int id = j * 256 + tid;
        int r = id / (CDS / 4), c = (id % (CDS / 4)) << 2;
        cp16(&cd[buf * (KC * CDS) + r * CDS + c],
             &g_cpad[(kbase + r) * CDS + c]);
    }
    cp_commit();
}

__global__ void __launch_bounds__(256, 2) assign_kernel() {
    float* xs = asg_smem;                       // [2][KC][256]
    float* cd = asg_smem + 2 * KC * 256;        // [2][KC][CDS]

    const int tid  = threadIdx.x;
    const int warp = tid >> 5, lane = tid & 31;
    const int mg = lane >> 3, ng = lane & 7;
    const int prow  = warp * 32 + mg * 8;       // first of 8 points (in tile)
    const int nbase = ng * 8;                   // first of 8 clusters
    const int ngoff = ng * 12;                  // padded chunk offset (floats, 48B)
    const unsigned pcta = blockIdx.x * 256u;

    asg_prefetch(xs, cd, 0, 0, pcta, tid);

    u64 acc[4][8];
#pragma unroll
    for (int m = 0; m < 4; ++m)
#pragma unroll
        for (int n = 0; n < 8; ++n) acc[m][n] = 0ull;

    for (int kc = 0; kc < NCH; ++kc) {
        const int buf = kc & 1;
        if (kc + 1 < NCH) {
            asg_prefetch(xs, cd, buf ^ 1, (kc + 1) * KC, pcta, tid);
            cp_wait<1>();
        } else {
            cp_wait<0>();
        }
        __syncthreads();

        const float* xr = xs + buf * (KC * 256);
        const float* cr = cd + buf * (KC * CDS);
#pragma unroll 8
        for (int k = 0; k < KC; ++k) {
            const ulonglong2 xp = *reinterpret_cast<const ulonglong2*>(&xr[(k << 8) + prow]);
            const ulonglong2 xq = *reinterpret_cast<const ulonglong2*>(&xr[(k << 8) + prow + 4]);
            const float4 c03 = *reinterpret_cast<const float4*>(&cr[k * CDS + ngoff]);
            const float4 c47 = *reinterpret_cast<const float4*>(&cr[k * CDS + ngoff + 4]);
            const u64 xv[4] = {xp.x, xp.y, xq.x, xq.y};
            const u64 cv[8] = {dup2(c03.x), dup2(c03.y), dup2(c03.z), dup2(c03.w),
                               dup2(c47.x), dup2(c47.y), dup2(c47.z), dup2(c47.w)};
#pragma unroll
            for (int m = 0; m < 4; ++m)
#pragma unroll
                for (int n = 0; n < 8; ++n)
                    acc[m][n] = f32x2_fma(xv[m], cv[n], acc[m][n]);
        }
        __syncthreads();
    }

    // epilogue: dist = ||c||^2 - 2*dot ; argmin with lowest-index tiebreak
    float cn[8];
#pragma unroll
    for (int n = 0; n < 8; ++n) cn[n] = g_cc[nbase + n];

#pragma unroll
    for (int m = 0; m < 8; ++m) {
        float best = __int_as_float(0x7f800000);   // +inf
        int bi = NK;
#pragma unroll
        for (int n = 0; n < 8; ++n) {
            float v0, v1;
            unpack2(acc[m >> 1][n], v0, v1);
            const float dot = (m & 1) ? v1 : v0;
            const float s = fmaf(-2.0f, dot, cn[n]);
            const int idx = nbase + n;
            if (s < best || (s == best && idx < bi)) { best = s; bi = idx; }
        }
#pragma unroll
        for (int off = 1; off < 8; off <<= 1) {
            const float ob = __shfl_xor_sync(0xffffffffu, best, off);
            const int   oi = __shfl_xor_sync(0xffffffffu, bi, off);
            if (ob < best || (ob == best && oi < bi)) { best = ob; bi = oi; }
        }
        if (ng == 0) g_labels[pcta + prow + m] = bi;
    }
}

// ---------------- segment-sum accumulation ---------------------------------
// 256 CTAs x 384 threads; thread t owns dim t -> conflict-free deterministic
// smem RMW. Coalesced streaming loads from original x[N][D].
extern __shared__ float acc_smem[];
__global__ void __launch_bounds__(384, 2) accum_kernel(const float* __restrict__ x) {
    __shared__ int s_lb[ACC_PTS];
    const int t = threadIdx.x;

    for (int i = t; i < NK * DIMS; i += 384) acc_smem[i] = 0.f;
    const int pbase = blockIdx.x * ACC_PTS;
    if (t < ACC_PTS) s_lb[t] = g_labels[pbase + t];
    __syncthreads();

    const float* xp = x + (size_t)pbase * DIMS + t;
    float cnt = 0.f;

    for (int j = 0; j < ACC_PTS; j += 32) {
        float v[32];
#pragma unroll
        for (int i = 0; i < 32; ++i)
            v[i] = __ldcs(xp + (unsigned)(j + i) * DIMS);   // streaming: keep L2 for g_xt
        int lb[32];
#pragma unroll
        for (int i = 0; i < 32; ++i)
            lb[i] = s_lb[j + i];
#pragma unroll
        for (int i = 0; i < 32; ++i) {
            acc_smem[lb[i] * DIMS + t] += v[i];
            cnt += (lb[i] == t) ? 1.f : 0.f;          // valid count for t < 64
        }
    }
    __syncthreads();

    float* outp = g_partials + (size_t)blockIdx.x * (NK * DIMS);
    for (int i = t; i < NK * DIMS; i += 384) outp[i] = acc_smem[i];
    if (t < NK) g_pcounts[t * ACC_CTAS + blockIdx.x] = cnt;
}

// ---------------- partials reduction -> new centers (192 CTAs) -------------
// CTA covers 128 consecutive dims of ONE cluster (384/128=3 CTAs per k).
// Counts are exact integers -> any summation order is bitwise deterministic.
__global__ void __launch_bounds__(128, 8) reduce_kernel() {
    __shared__ float sc[128];
    const int k = blockIdx.x / 3;
    const int d = (blockIdx.x % 3) * 128 + threadIdx.x;
    const int e = k * DIMS + d;

    sc[threadIdx.x] = g_pcounts[k * ACC_CTAS + threadIdx.x]
                    + g_pcounts[k * ACC_CTAS + threadIdx.x + 128];

    const float* pp = g_partials + e;
    float sum = 0.f;
    for (int c = 0; c < ACC_CTAS; c += 16) {
#pragma unroll
        for (int i = 0; i < 16; ++i)
            sum += __ldg(pp + (size_t)(c + i) * (NK * DIMS));
    }

    __syncthreads();
    for (int s = 64; s > 0; s >>= 1) {
        if (threadIdx.x < s) sc[threadIdx.x] += sc[threadIdx.x + s];
        __syncthreads();
    }
    const float cnt = sc[0];

    const float v = (cnt > 0.f) ? (sum / fmaxf(cnt, 1.f)) : g_centers[e];
    g_centers[e] = v;
    g_cpad[d * CDS + (k >> 3) * 12 + (k & 7)] = v;
}

// ---------------- finish: ||c||^2 -------------------------------------------
__global__ void __launch_bounds__(DIMS, 1) finish_kernel() {
    __shared__ float red[DIMS];
    const int k = blockIdx.x, t = threadIdx.x;
    const float v = g_centers[k * DIMS + t];
    red[t] = v * v;
    __syncthreads();
    for (int s = 256; s > 0; s >>= 1) {
        if (t < s && t + s < DIMS) red[t] += red[t + s];
        __syncthreads();
    }
    if (t == 0) g_cc[k] = red[0];
}

// ---------------- proj = centers @ W^T + b ---------------------------------
__global__ void proj_kernel(const float* __restrict__ W, const float* __restrict__ b) {
    __shared__ float cs[DIMS];
    const int k = blockIdx.x, d = threadIdx.x;
    cs[d] = g_centers[k * DIMS + d];
    __syncthreads();
    const float4* Wr = reinterpret_cast<const float4*>(W + (size_t)d * DIMS);
    float acc = 0.f;
#pragma unroll 4
    for (int i = 0; i < DIMS / 4; ++i) {
        const float4 w = Wr[i];
        acc += cs[4 * i] * w.x + cs[4 * i + 1] * w.y
             + cs[4 * i + 2] * w.z + cs[4 * i + 3] * w.w;
    }
    g_proj[k * DIMS + d] = acc + b[d];
}

// ---------------- scatter out[p] = proj[label[p]] --------------------------
__global__ void scatter_kernel(float* __restrict__ out) {
    const unsigned idx = blockIdx.x * 256u + threadIdx.x;   // float4 index
    const int p = idx / (DIMS / 4), r = idx % (DIMS / 4);
    const int lb = g_labels[p];
    reinterpret_cast<float4*>(out)[idx] =
        reinterpret_cast<const float4*>(g_proj)[lb * (DIMS / 4) + r];
}

// ---------------- launch ----------------------------------------------------
extern "C" void kernel_launch(void* const* d_in, const int* in_sizes, int n_in,
                              void* d_out, int out_size) {
    const float* x = (const float*)d_in[0];
    const float* W = (const float*)d_in[1];
    const float* b = (const float*)d_in[2];
    float* out = (float*)d_out;

    const int asg_smem_bytes = (2 * KC * 256 + 2 * KC * CDS) * (int)sizeof(float); // 90112
    const int acc_smem_bytes = NK * DIMS * (int)sizeof(float);                      // 98304

    cudaFuncSetAttribute(assign_kernel, cudaFuncAttributeMaxDynamicSharedMemorySize,
                         asg_smem_bytes);
    cudaFuncSetAttribute(accum_kernel, cudaFuncAttributeMaxDynamicSharedMemorySize,
                         acc_smem_bytes);

    transpose_kernel<<<dim3(DIMS / 32, NPTS / 32), dim3(32, 8)>>>(x);
    init_centers_kernel<<<NK, DIMS>>>(x);

    for (int it = 0; it < ITERS; ++it) {
        assign_kernel<<<NPTS / 256, 256, asg_smem_bytes>>>();
        accum_kernel<<<ACC_CTAS, 384, acc_smem_bytes>>>(x);
        reduce_kernel<<<3 * NK, 128>>>();
        finish_kernel<<<NK, DIMS>>>();
    }
    assign_kernel<<<NPTS / 256, 256, asg_smem_bytes>>>();

    proj_kernel<<<NK, DIMS>>>(W, b);
    scatter_kernel<<<(NPTS * (DIMS / 4)) / 256, 256>>>(out);
}

// round 9
// speedup vs baseline: 1.1865x; 1.1108x over previous
#include <cuda_runtime.h>
#include <cstdint>

#define NPTS   65536
#define DIMS   384
#define NK     64
#define ITERS  10
#define NCH    12            // 12 chunks x 32 dims
#define ACC_CTAS 256
#define ACC_PTS  256

typedef unsigned long long u64;

// ---------------- scratch -----------------------------------------------------
__device__ float g_centers[NK * DIMS];
__device__ __align__(16) float g_cfh[48 * 512];   // B fragments (hi): [s][j][lane][2]
__device__ __align__(16) float g_cfl[48 * 512];   // B fragments (lo)
__device__ float g_cc[NK];
__device__ int   g_labels[NPTS];
__device__ float g_partials[(size_t)ACC_CTAS * NK * DIMS];
__device__ float g_pcounts[NK * ACC_CTAS];
__device__ float g_proj[NK * DIMS];

// ---------------- helpers ------------------------------------------------------
__device__ __forceinline__ uint32_t tf32_rna(float v) {
    uint32_t r;
    asm("cvt.rna.tf32.f32 %0, %1;" : "=r"(r) : "f"(v));
    return r;
}
__device__ __forceinline__ void cp16(const void* smem, const void* gmem) {
    unsigned sa = (unsigned)__cvta_generic_to_shared(smem);
    asm volatile("cp.async.cg.shared.global [%0], [%1], 16;" :: "r"(sa), "l"(gmem));
}
__device__ __forceinline__ void cp_commit() { asm volatile("cp.async.commit_group;"); }
template <int N>
__device__ __forceinline__ void cp_wait() { asm volatile("cp.async.wait_group %0;" :: "n"(N)); }

__device__ __forceinline__ void mma8(float* d, const uint32_t* a, uint32_t b0, uint32_t b1) {
    asm("mma.sync.aligned.m16n8k8.row.col.f32.tf32.tf32.f32 "
        "{%0,%1,%2,%3},{%4,%5,%6,%7},{%8,%9},{%0,%1,%2,%3};"
        : "+f"(d[0]), "+f"(d[1]), "+f"(d[2]), "+f"(d[3])
        : "r"(a[0]), "r"(a[1]), "r"(a[2]), "r"(a[3]), "r"(b0), "r"(b1));
}

// B-fragment position for (cluster k, dim d):
//   s = d>>3, j = k>>3, lane = (k&7)*4 + (d&3), i = (d&7)>>2
__device__ __forceinline__ void store_center_frag(int k, int d, float v) {
    const int s = d >> 3, j = k >> 3;
    const int lane = (k & 7) * 4 + (d & 3);
    const int i = (d & 7) >> 2;
    const int off = ((s * 8 + j) * 32 + lane) * 2 + i;
    const uint32_t h = tf32_rna(v);
    const float lof = v - __uint_as_float(h);
    g_cfh[off] = __uint_as_float(h);
    g_cfl[off] = __uint_as_float(tf32_rna(lof));
}

// ---------------- init centers = first 64 points ------------------------------
__global__ void init_centers_kernel(const float* __restrict__ x) {
    __shared__ float red[DIMS];
    int k = blockIdx.x, d = threadIdx.x;
    float v = x[k * DIMS + d];
    g_centers[k * DIMS + d] = v;
    store_center_frag(k, d, v);
    red[d] = v * v;
    __syncthreads();
    for (int s = 256; s > 0; s >>= 1) {
        if (d < s && d + s < DIMS) red[d] += red[d + s];
        __syncthreads();
    }
    if (d == 0) g_cc[k] = red[0];
}

// ---------------- assignment via mma.sync 3xTF32 -------------------------------
// 512 CTAs x 256 threads (8 warps). CTA = 128 points x 64 clusters.
// smem float offsets per buffer (buf stride 12288 floats = 48KB):
//   A_hi [4 ksteps][8 w][32 lanes(rotated)][4]   : 0     .. 4096
//   A_lo                                          : 4096  .. 8192
//   B_hi [4 ksteps][8 j][32 lanes][2]             : 8192  .. 10240
//   B_lo                                          : 10240 .. 12288
extern __shared__ float asg_sm[];

__global__ void __launch_bounds__(256, 2) assign_kernel(const float* __restrict__ x) {
    __shared__ float scc[NK];
    const int tid = threadIdx.x;
    const int wid = tid >> 5, lane = tid & 31;
    const unsigned pcta = blockIdx.x * 128u;

    if (tid < NK) scc[tid] = g_cc[tid];

    // issue B cp.async for chunks 0 and 1
#pragma unroll
    for (int c0 = 0; c0 < 2; ++c0) {
        float* bh = asg_sm + c0 * 12288 + 8192;
        float* bl = asg_sm + c0 * 12288 + 10240;
        const char* sh = (const char*)(g_cfh + c0 * 2048);
        const char* sl = (const char*)(g_cfl + c0 * 2048);
#pragma unroll
        for (int t = 0; t < 2; ++t) {
            cp16((char*)bh + (tid + 256 * t) * 16, sh + (tid + 256 * t) * 16);
            cp16((char*)bl + (tid + 256 * t) * 16, sl + (tid + 256 * t) * 16);
        }
        cp_commit();
    }

    // prefetch x chunk 0: 4 pieces per thread
    const int ptb = tid >> 3;         // base point / 4 groups of 32
    const int fq  = tid & 7;          // float4 index within 32-dim chunk
    float4 rx[4], rn[4];
#pragma unroll
    for (int q = 0; q < 4; ++q) {
        const int pt = ptb + 32 * q;
        rx[q] = *reinterpret_cast<const float4*>(&x[(size_t)(pcta + pt) * DIMS + fq * 4]);
    }

    float D[8][4];
#pragma unroll
    for (int j = 0; j < 8; ++j)
#pragma unroll
        for (int t = 0; t < 4; ++t) D[j][t] = 0.f;

    for (int c = 0; c < NCH; ++c) {
        const int buf = c & 1;
        float* SAH = asg_sm + buf * 12288;
        float* SAL = SAH + 4096;
        const float* SBH = SAH + 8192;
        const float* SBL = SAH + 10240;

        if (c < NCH - 2) cp_wait<1>(); else cp_wait<0>();

        // producer: split x chunk c into A fragments (rotated layout)
        const int slocal = fq >> 1, ii = fq & 1;
#pragma unroll
        for (int q = 0; q < 4; ++q) {
            const int pt = ptb + 32 * q;
            const int w = pt >> 4, rr = pt & 15;
            const int rhalf = rr >> 3;
            const float xe[4] = {rx[q].x, rx[q].y, rx[q].z, rx[q].w};
#pragma unroll
            for (int e = 0; e < 4; ++e) {
                const int lane_t = (rr & 7) * 4 + e;
                const int rot = (lane_t + slocal) & 31;
                const int off = (slocal * 8 + w) * 128 + rot * 4 + ii * 2 + rhalf;
                const uint32_t h = tf32_rna(xe[e]);
                const float lof = xe[e] - __uint_as_float(h);
                SAH[off] = __uint_as_float(h);
                SAL[off] = __uint_as_float(tf32_rna(lof));
            }
        }

        // prefetch x chunk c+1
        if (c + 1 < NCH) {
#pragma unroll
            for (int q = 0; q < 4; ++q) {
                const int pt = ptb + 32 * q;
                rn[q] = *reinterpret_cast<const float4*>(
                    &x[(size_t)(pcta + pt) * DIMS + (c + 1) * 32 + fq * 4]);
            }
        }

        __syncthreads();

        // MMA: 4 ksteps x 8 ntiles x 3 (3xTF32)
#pragma unroll
        for (int s = 0; s < 4; ++s) {
            const int arot = ((lane + s) & 31) * 4;
            uint32_t a[4], al[4];
            *reinterpret_cast<uint4*>(a) =
                *reinterpret_cast<const uint4*>(&SAH[(s * 8 + wid) * 128 + arot]);
            *reinterpret_cast<uint4*>(al) =
                *reinterpret_cast<const uint4*>(&SAL[(s * 8 + wid) * 128 + arot]);
#pragma unroll
            for (int j = 0; j < 8; ++j) {
                const uint2 bh = *reinterpret_cast<const uint2*>(&SBH[(s * 8 + j) * 64 + lane * 2]);
                const uint2 bl = *reinterpret_cast<const uint2*>(&SBL[(s * 8 + j) * 64 + lane * 2]);
                mma8(D[j], a, bh.x, bh.y);
                mma8(D[j], a, bl.x, bl.y);
                mma8(D[j], al, bh.x, bh.y);
            }
        }
        __syncthreads();

        // issue B cp.async for chunk c+2 into this buffer
        if (c + 2 < NCH) {
            float* bh = asg_sm + buf * 12288 + 8192;
            float* bl = asg_sm + buf * 12288 + 10240;
            const char* sh = (const char*)(g_cfh + (c + 2) * 2048);
            const char* sl = (const char*)(g_cfl + (c + 2) * 2048);
#pragma unroll
            for (int t = 0; t < 2; ++t) {
                cp16((char*)bh + (tid + 256 * t) * 16, sh + (tid + 256 * t) * 16);
                cp16((char*)bl + (tid + 256 * t) * 16, sl + (tid + 256 * t) * 16);
            }
            cp_commit();
        }
#pragma unroll
        for (int q = 0; q < 4; ++q) rx[q] = rn[q];
    }

    // epilogue: dist = cc[n] - 2*dot ; argmin, first-min tiebreak
    float best0 = __int_as_float(0x7f800000), best1 = best0;
    int bi0 = NK, bi1 = NK;
#pragma unroll
    for (int j = 0; j < 8; ++j) {
#pragma unroll
        for (int t = 0; t < 2; ++t) {
            const int n = j * 8 + (lane & 3) * 2 + t;
            const float cc = scc[n];
            const float s0 = fmaf(-2.0f, D[j][t], cc);
            const float s1 = fmaf(-2.0f, D[j][2 + t], cc);
            if (s0 < best0 || (s0 == best0 && n < bi0)) { best0 = s0; bi0 = n; }
            if (s1 < best1 || (s1 == best1 && n < bi1)) { best1 = s1; bi1 = n; }
        }
    }
#pragma unroll
    for (int off = 1; off < 4; off <<= 1) {
        float ob = __shfl_xor_sync(0xffffffffu, best0, off);
        int   oi = __shfl_xor_sync(0xffffffffu, bi0, off);
        if (ob < best0 || (ob == best0 && oi < bi0)) { best0 = ob; bi0 = oi; }
        ob = __shfl_xor_sync(0xffffffffu, best1, off);
        oi = __shfl_xor_sync(0xffffffffu, bi1, off);
        if (ob < best1 || (ob == best1 && oi < bi1)) { best1 = ob; bi1 = oi; }
    }
    if ((lane & 3) == 0) {
        const int r = lane >> 2;
        const unsigned p0 = pcta + wid * 16;
        g_labels[p0 + r] = bi0;
        g_labels[p0 + r + 8] = bi1;
    }
}

// ---------------- segment-sum accumulation (x now L2-resident) ----------------
extern __shared__ float acc_smem[];
__global__ void __launch_bounds__(384, 2) accum_kernel(const float* __restrict__ x) {
    __shared__ int s_lb[ACC_PTS];
    const int t = threadIdx.x;

    for (int i = t; i < NK * DIMS; i += 384) acc_smem[i] = 0.f;
    const int pbase = blockIdx.x * ACC_PTS;
    if (t < ACC_PTS) s_lb[t] = g_labels[pbase + t];
    __syncthreads();

    const float* xp = x + (size_t)pbase * DIMS + t;
    float cnt = 0.f;

    for (int j = 0; j < ACC_PTS; j += 32) {
        float v[32];
#pragma unroll
        for (int i = 0; i < 32; ++i)
            v[i] = __ldg(xp + (unsigned)(j + i) * DIMS);
        int lb[32];
#pragma unroll
        for (int i = 0; i < 32; ++i)
            lb[i] = s_lb[j + i];
#pragma unroll
        for (int i = 0; i < 32; ++i) {
            acc_smem[lb[i] * DIMS + t] += v[i];
            cnt += (lb[i] == t) ? 1.f : 0.f;
        }
    }
    __syncthreads();

    float* outp = g_partials + (size_t)blockIdx.x * (NK * DIMS);
    for (int i = t; i < NK * DIMS; i += 384) outp[i] = acc_smem[i];
    if (t < NK) g_pcounts[t * ACC_CTAS + blockIdx.x] = cnt;
}

// ---------------- partials reduction -> new centers ----------------------------
__global__ void __launch_bounds__(128, 8) reduce_kernel() {
    __shared__ float sc[128];
    const int k = blockIdx.x / 3;
    const int d = (blockIdx.x % 3) * 128 + threadIdx.x;
    const int e = k * DIMS + d;

    sc[threadIdx.x] = g_pcounts[k * ACC_CTAS + threadIdx.x]
                    + g_pcounts[k * ACC_CTAS + threadIdx.x + 128];

    const float* pp = g_partials + e;
    float sum = 0.f;
    for (int c = 0; c < ACC_CTAS; c += 16) {
#pragma unroll
        for (int i = 0; i < 16; ++i)
            sum += __ldg(pp + (size_t)(c + i) * (NK * DIMS));
    }

    __syncthreads();
    for (int s = 64; s > 0; s >>= 1) {
        if (threadIdx.x < s) sc[threadIdx.x] += sc[threadIdx.x + s];
        __syncthreads();
    }
    const float cnt = sc[0];

    const float v = (cnt > 0.f) ? (sum / fmaxf(cnt, 1.f)) : g_centers[e];
    g_centers[e] = v;
    store_center_frag(k, d, v);
}

// ---------------- finish: ||c||^2 ----------------------------------------------
__global__ void __launch_bounds__(DIMS, 1) finish_kernel() {
    __shared__ float red[DIMS];
    const int k = blockIdx.x, t = threadIdx.x;
    const float v = g_centers[k * DIMS + t];
    red[t] = v * v;
    __syncthreads();
    for (int s = 256; s > 0; s >>= 1) {
        if (t < s && t + s < DIMS) red[t] += red[t + s];
        __syncthreads();
    }
    if (t == 0) g_cc[k] = red[0];
}

// ---------------- proj = centers @ W^T + b --------------------------------------
__global__ void proj_kernel(const float* __restrict__ W, const float* __restrict__ b) {
    __shared__ float cs[DIMS];
    const int k = blockIdx.x, d = threadIdx.x;
    cs[d] = g_centers[k * DIMS + d];
    __syncthreads();
    const float4* Wr = reinterpret_cast<const float4*>(W + (size_t)d * DIMS);
    float acc = 0.f;
#pragma unroll 4
    for (int i = 0; i < DIMS / 4; ++i) {
        const float4 w = Wr[i];
        acc += cs[4 * i] * w.x + cs[4 * i + 1] * w.y
             + cs[4 * i + 2] * w.z + cs[4 * i + 3] * w.w;
    }
    g_proj[k * DIMS + d] = acc + b[d];
}

// ---------------- scatter out[p] = proj[label[p]] -------------------------------
__global__ void scatter_kernel(float* __restrict__ out) {
    const unsigned idx = blockIdx.x * 256u + threadIdx.x;
    const int p = idx / (DIMS / 4), r = idx % (DIMS / 4);
    const int lb = g_labels[p];
    reinterpret_cast<float4*>(out)[idx] =
        reinterpret_cast<const float4*>(g_proj)[lb * (DIMS / 4) + r];
}

// ---------------- launch ----------------------------------------------------------
extern "C" void kernel_launch(void* const* d_in, const int* in_sizes, int n_in,
                              void* d_out, int out_size) {
    const float* x = (const float*)d_in[0];
    const float* W = (const float*)d_in[1];
    const float* b = (const float*)d_in[2];
    float* out = (float*)d_out;

    const int asg_smem_bytes = 2 * 12288 * (int)sizeof(float);   // 98304
    const int acc_smem_bytes = NK * DIMS * (int)sizeof(float);   // 98304

    cudaFuncSetAttribute(assign_kernel, cudaFuncAttributeMaxDynamicSharedMemorySize,
                         asg_smem_bytes);
    cudaFuncSetAttribute(accum_kernel, cudaFuncAttributeMaxDynamicSharedMemorySize,
                         acc_smem_bytes);

    init_centers_kernel<<<NK, DIMS>>>(x);

    for (int it = 0; it < ITERS; ++it) {
        assign_kernel<<<NPTS / 128, 256, asg_smem_bytes>>>(x);
        accum_kernel<<<ACC_CTAS, 384, acc_smem_bytes>>>(x);
        reduce_kernel<<<3 * NK, 128>>>();
        finish_kernel<<<NK, DIMS>>>();
    }
    assign_kernel<<<NPTS / 128, 256, asg_smem_bytes>>>(x);

    proj_kernel<<<NK, DIMS>>>(W, b);
    scatter_kernel<<<(NPTS * (DIMS / 4)) / 256, 256>>>(out);
}

// round 10
// speedup vs baseline: 1.2168x; 1.0255x over previous
#include <cuda_runtime.h>
#include <cstdint>

#define NPTS   65536
#define DIMS   384
#define NK     64
#define ITERS  10
#define NCH    12            // 12 chunks x 32 dims
#define ACC_CTAS 256
#define ACC_PTS  256

typedef unsigned long long u64;

// ---------------- scratch -----------------------------------------------------
__device__ float g_centers[NK * DIMS];
__device__ __align__(16) float g_cfh[48 * 512];   // B fragments (hi): [s][j][lane][2]
__device__ __align__(16) float g_cfl[48 * 512];   // B fragments (lo)
__device__ float g_cc[NK];
__device__ int   g_labels[NPTS];
__device__ float g_partials[(size_t)ACC_CTAS * NK * DIMS];
__device__ float g_pcounts[NK * ACC_CTAS];
__device__ float g_proj[NK * DIMS];

// ---------------- helpers ------------------------------------------------------
__device__ __forceinline__ uint32_t tf32_rna(float v) {
    uint32_t r;
    asm("cvt.rna.tf32.f32 %0, %1;" : "=r"(r) : "f"(v));
    return r;
}
__device__ __forceinline__ void cp16(const void* smem, const void* gmem) {
    unsigned sa = (unsigned)__cvta_generic_to_shared(smem);
    asm volatile("cp.async.cg.shared.global [%0], [%1], 16;" :: "r"(sa), "l"(gmem));
}
__device__ __forceinline__ void cp_commit() { asm volatile("cp.async.commit_group;"); }
template <int N>
__device__ __forceinline__ void cp_wait() { asm volatile("cp.async.wait_group %0;" :: "n"(N)); }

__device__ __forceinline__ void mma8(float* d, const uint32_t* a, uint32_t b0, uint32_t b1) {
    asm("mma.sync.aligned.m16n8k8.row.col.f32.tf32.tf32.f32 "
        "{%0,%1,%2,%3},{%4,%5,%6,%7},{%8,%9},{%0,%1,%2,%3};"
        : "+f"(d[0]), "+f"(d[1]), "+f"(d[2]), "+f"(d[3])
        : "r"(a[0]), "r"(a[1]), "r"(a[2]), "r"(a[3]), "r"(b0), "r"(b1));
}

// B-fragment position for (cluster k, dim d):
//   s = d>>3, j = k>>3, lane = (k&7)*4 + (d&3), i = (d&7)>>2
__device__ __forceinline__ void store_center_frag(int k, int d, float v) {
    const int s = d >> 3, j = k >> 3;
    const int lane = (k & 7) * 4 + (d & 3);
    const int i = (d & 7) >> 2;
    const int off = ((s * 8 + j) * 32 + lane) * 2 + i;
    const uint32_t h = tf32_rna(v);
    const float lof = v - __uint_as_float(h);
    g_cfh[off] = __uint_as_float(h);
    g_cfl[off] = __uint_as_float(tf32_rna(lof));
}

// ---------------- init centers = first 64 points ------------------------------
__global__ void init_centers_kernel(const float* __restrict__ x) {
    __shared__ float red[DIMS];
    int k = blockIdx.x, d = threadIdx.x;
    float v = x[k * DIMS + d];
    g_centers[k * DIMS + d] = v;
    store_center_frag(k, d, v);
    red[d] = v * v;
    __syncthreads();
    for (int s = 256; s > 0; s >>= 1) {
        if (d < s && d + s < DIMS) red[d] += red[d + s];
        __syncthreads();
    }
    if (d == 0) g_cc[k] = red[0];
}

// ---------------- assignment via mma.sync 3xTF32 -------------------------------
// 512 CTAs x 256 threads (8 warps). CTA = 128 points x 64 clusters.
extern __shared__ float asg_sm[];

__global__ void __launch_bounds__(256, 2) assign_kernel(const float* __restrict__ x) {
    __shared__ float scc[NK];
    const int tid = threadIdx.x;
    const int wid = tid >> 5, lane = tid & 31;
    const unsigned pcta = blockIdx.x * 128u;

    if (tid < NK) scc[tid] = g_cc[tid];

    // issue B cp.async for chunks 0 and 1
#pragma unroll
    for (int c0 = 0; c0 < 2; ++c0) {
        float* bh = asg_sm + c0 * 12288 + 8192;
        float* bl = asg_sm + c0 * 12288 + 10240;
        const char* sh = (const char*)(g_cfh + c0 * 2048);
        const char* sl = (const char*)(g_cfl + c0 * 2048);
#pragma unroll
        for (int t = 0; t < 2; ++t) {
            cp16((char*)bh + (tid + 256 * t) * 16, sh + (tid + 256 * t) * 16);
            cp16((char*)bl + (tid + 256 * t) * 16, sl + (tid + 256 * t) * 16);
        }
        cp_commit();
    }

    // prefetch x chunk 0: 4 pieces per thread
    const int ptb = tid >> 3;
    const int fq  = tid & 7;
    float4 rx[4], rn[4];
#pragma unroll
    for (int q = 0; q < 4; ++q) {
        const int pt = ptb + 32 * q;
        rx[q] = *reinterpret_cast<const float4*>(&x[(size_t)(pcta + pt) * DIMS + fq * 4]);
    }

    float D[8][4];
#pragma unroll
    for (int j = 0; j < 8; ++j)
#pragma unroll
        for (int t = 0; t < 4; ++t) D[j][t] = 0.f;

    for (int c = 0; c < NCH; ++c) {
        const int buf = c & 1;
        float* SAH = asg_sm + buf * 12288;
        float* SAL = SAH + 4096;
        const float* SBH = SAH + 8192;
        const float* SBL = SAH + 10240;

        if (c < NCH - 2) cp_wait<1>(); else cp_wait<0>();

        // producer: split x chunk c into A fragments (rotated layout)
        const int slocal = fq >> 1, ii = fq & 1;
#pragma unroll
        for (int q = 0; q < 4; ++q) {
            const int pt = ptb + 32 * q;
            const int w = pt >> 4, rr = pt & 15;
            const int rhalf = rr >> 3;
            const float xe[4] = {rx[q].x, rx[q].y, rx[q].z, rx[q].w};
#pragma unroll
            for (int e = 0; e < 4; ++e) {
                const int lane_t = (rr & 7) * 4 + e;
                const int rot = (lane_t + slocal) & 31;
                const int off = (slocal * 8 + w) * 128 + rot * 4 + ii * 2 + rhalf;
                const uint32_t h = tf32_rna(xe[e]);
                const float lof = xe[e] - __uint_as_float(h);
                SAH[off] = __uint_as_float(h);
                SAL[off] = __uint_as_float(tf32_rna(lof));
            }
        }

        // prefetch x chunk c+1
        if (c + 1 < NCH) {
#pragma unroll
            for (int q = 0; q < 4; ++q) {
                const int pt = ptb + 32 * q;
                rn[q] = *reinterpret_cast<const float4*>(
                    &x[(size_t)(pcta + pt) * DIMS + (c + 1) * 32 + fq * 4]);
            }
        }

        __syncthreads();

        // MMA: 4 ksteps x 8 ntiles x 3 (3xTF32)
#pragma unroll
        for (int s = 0; s < 4; ++s) {
            const int arot = ((lane + s) & 31) * 4;
            uint32_t a[4], al[4];
            *reinterpret_cast<uint4*>(a) =
                *reinterpret_cast<const uint4*>(&SAH[(s * 8 + wid) * 128 + arot]);
            *reinterpret_cast<uint4*>(al) =
                *reinterpret_cast<const uint4*>(&SAL[(s * 8 + wid) * 128 + arot]);
#pragma unroll
            for (int j = 0; j < 8; ++j) {
                const uint2 bh = *reinterpret_cast<const uint2*>(&SBH[(s * 8 + j) * 64 + lane * 2]);
                const uint2 bl = *reinterpret_cast<const uint2*>(&SBL[(s * 8 + j) * 64 + lane * 2]);
                mma8(D[j], a, bh.x, bh.y);
                mma8(D[j], a, bl.x, bl.y);
                mma8(D[j], al, bh.x, bh.y);
            }
        }
        __syncthreads();

        // issue B cp.async for chunk c+2 into this buffer
        if (c + 2 < NCH) {
            float* bh = asg_sm + buf * 12288 + 8192;
            float* bl = asg_sm + buf * 12288 + 10240;
            const char* sh = (const char*)(g_cfh + (c + 2) * 2048);
            const char* sl = (const char*)(g_cfl + (c + 2) * 2048);
#pragma unroll
            for (int t = 0; t < 2; ++t) {
                cp16((char*)bh + (tid + 256 * t) * 16, sh + (tid + 256 * t) * 16);
                cp16((char*)bl + (tid + 256 * t) * 16, sl + (tid + 256 * t) * 16);
            }
            cp_commit();
        }
#pragma unroll
        for (int q = 0; q < 4; ++q) rx[q] = rn[q];
    }

    // epilogue: dist = cc[n] - 2*dot ; argmin, first-min tiebreak
    float best0 = __int_as_float(0x7f800000), best1 = best0;
    int bi0 = NK, bi1 = NK;
#pragma unroll
    for (int j = 0; j < 8; ++j) {
#pragma unroll
        for (int t = 0; t < 2; ++t) {
            const int n = j * 8 + (lane & 3) * 2 + t;
            const float cc = scc[n];
            const float s0 = fmaf(-2.0f, D[j][t], cc);
            const float s1 = fmaf(-2.0f, D[j][2 + t], cc);
            if (s0 < best0 || (s0 == best0 && n < bi0)) { best0 = s0; bi0 = n; }
            if (s1 < best1 || (s1 == best1 && n < bi1)) { best1 = s1; bi1 = n; }
        }
    }
#pragma unroll
    for (int off = 1; off < 4; off <<= 1) {
        float ob = __shfl_xor_sync(0xffffffffu, best0, off);
        int   oi = __shfl_xor_sync(0xffffffffu, bi0, off);
        if (ob < best0 || (ob == best0 && oi < bi0)) { best0 = ob; bi0 = oi; }
        ob = __shfl_xor_sync(0xffffffffu, best1, off);
        oi = __shfl_xor_sync(0xffffffffu, bi1, off);
        if (ob < best1 || (ob == best1 && oi < bi1)) { best1 = ob; bi1 = oi; }
    }
    if ((lane & 3) == 0) {
        const int r = lane >> 2;
        const unsigned p0 = pcta + wid * 16;
        g_labels[p0 + r] = bi0;
        g_labels[p0 + r + 8] = bi1;
    }
}

// ---------------- segment-sum accumulation --------------------------------------
extern __shared__ float acc_smem[];
__global__ void __launch_bounds__(384, 2) accum_kernel(const float* __restrict__ x) {
    __shared__ int s_lb[ACC_PTS];
    const int t = threadIdx.x;

    for (int i = t; i < NK * DIMS; i += 384) acc_smem[i] = 0.f;
    const int pbase = blockIdx.x * ACC_PTS;
    if (t < ACC_PTS) s_lb[t] = g_labels[pbase + t];
    __syncthreads();

    const float* xp = x + (size_t)pbase * DIMS + t;
    float cnt = 0.f;

    for (int j = 0; j < ACC_PTS; j += 32) {
        float v[32];
#pragma unroll
        for (int i = 0; i < 32; ++i)
            v[i] = __ldg(xp + (unsigned)(j + i) * DIMS);
        int lb[32];
#pragma unroll
        for (int i = 0; i < 32; ++i)
            lb[i] = s_lb[j + i];
#pragma unroll
        for (int i = 0; i < 32; ++i) {
            acc_smem[lb[i] * DIMS + t] += v[i];
            cnt += (lb[i] == t) ? 1.f : 0.f;
        }
    }
    __syncthreads();

    float* outp = g_partials + (size_t)blockIdx.x * (NK * DIMS);
    for (int i = t; i < NK * DIMS; i += 384) outp[i] = acc_smem[i];
    if (t < NK) g_pcounts[t * ACC_CTAS + blockIdx.x] = cnt;
}

// ---------------- partials reduction -> new centers ------------------------------
// 384 CTAs x 256 threads. CTA b: cluster k = b/6, dims dp*64..dp*64+63.
// 4 thread-groups of 64 each sum 64 partials (coalesced, unroll 16); fixed-order
// 4-way combine. Counts block-reduced (exact integers -> order-free).
__global__ void __launch_bounds__(256, 4) reduce_kernel() {
    __shared__ float sp[256];
    __shared__ float sv[4][64];
    const int b = blockIdx.x;
    const int k = b / 6, dp = b % 6;
    const int t = threadIdx.x;
    const int g = t >> 6, e = t & 63;
    const int d = dp * 64 + e;

    sp[t] = g_pcounts[k * ACC_CTAS + t];

    const float* pp = g_partials + (size_t)(g * 64) * (NK * DIMS) + k * DIMS + d;
    float s = 0.f;
    for (int c = 0; c < 64; c += 16) {
#pragma unroll
        for (int i = 0; i < 16; ++i)
            s += __ldg(pp + (size_t)(c + i) * (NK * DIMS));
    }
    sv[g][e] = s;
    __syncthreads();

    for (int st = 128; st > 0; st >>= 1) {
        if (t < st) sp[t] += sp[t + st];
        __syncthreads();
    }
    const float cnt = sp[0];

    if (t < 64) {
        const float sum = ((sv[0][t] + sv[1][t]) + sv[2][t]) + sv[3][t];
        const int dd = dp * 64 + t;
        const int ee = k * DIMS + dd;
        const float v = (cnt > 0.f) ? (sum / fmaxf(cnt, 1.f)) : g_centers[ee];
        g_centers[ee] = v;
        store_center_frag(k, dd, v);
    }
}

// ---------------- finish: ||c||^2 -------------------------------------------------
__global__ void __launch_bounds__(DIMS, 1) finish_kernel() {
    __shared__ float red[DIMS];
    const int k = blockIdx.x, t = threadIdx.x;
    const float v = g_centers[k * DIMS + t];
    red[t] = v * v;
    __syncthreads();
    for (int s = 256; s > 0; s >>= 1) {
        if (t < s && t + s < DIMS) red[t] += red[t + s];
        __syncthreads();
    }
    if (t == 0) g_cc[k] = red[0];
}

// ---------------- proj = centers @ W^T + b ----------------------------------------
__global__ void proj_kernel(const float* __restrict__ W, const float* __restrict__ b) {
    __shared__ float cs[DIMS];
    const int k = blockIdx.x, d = threadIdx.x;
    cs[d] = g_centers[k * DIMS + d];
    __syncthreads();
    const float4* Wr = reinterpret_cast<const float4*>(W + (size_t)d * DIMS);
    float acc = 0.f;
#pragma unroll 4
    for (int i = 0; i < DIMS / 4; ++i) {
        const float4 w = Wr[i];
        acc += cs[4 * i] * w.x + cs[4 * i + 1] * w.y
             + cs[4 * i + 2] * w.z + cs[4 * i + 3] * w.w;
    }
    g_proj[k * DIMS + d] = acc + b[d];
}

// ---------------- scatter out[p] = proj[label[p]] ---------------------------------
__global__ void scatter_kernel(float* __restrict__ out) {
    const unsigned idx = blockIdx.x * 256u + threadIdx.x;
    const int p = idx / (DIMS / 4), r = idx % (DIMS / 4);
    const int lb = g_labels[p];
    reinterpret_cast<float4*>(out)[idx] =
        reinterpret_cast<const float4*>(g_proj)[lb * (DIMS / 4) + r];
}

// ---------------- launch ------------------------------------------------------------
extern "C" void kernel_launch(void* const* d_in, const int* in_sizes, int n_in,
                              void* d_out, int out_size) {
    const float* x = (const float*)d_in[0];
    const float* W = (const float*)d_in[1];
    const float* b = (const float*)d_in[2];
    float* out = (float*)d_out;

    const int asg_smem_bytes = 2 * 12288 * (int)sizeof(float);   // 98304
    const int acc_smem_bytes = NK * DIMS * (int)sizeof(float);   // 98304

    cudaFuncSetAttribute(assign_kernel, cudaFuncAttributeMaxDynamicSharedMemorySize,
                         asg_smem_bytes);
    cudaFuncSetAttribute(accum_kernel, cudaFuncAttributeMaxDynamicSharedMemorySize,
                         acc_smem_bytes);

    init_centers_kernel<<<NK, DIMS>>>(x);

    for (int it = 0; it < ITERS; ++it) {
        assign_kernel<<<NPTS / 128, 256, asg_smem_bytes>>>(x);
        accum_kernel<<<ACC_CTAS, 384, acc_smem_bytes>>>(x);
        reduce_kernel<<<6 * NK, 256>>>();
        finish_kernel<<<NK, DIMS>>>();
    }
    assign_kernel<<<NPTS / 128, 256, asg_smem_bytes>>>(x);

    proj_kernel<<<NK, DIMS>>>(W, b);
    scatter_kernel<<<(NPTS * (DIMS / 4)) / 256, 256>>>(out);
}

// round 12
// speedup vs baseline: 1.7065x; 1.4025x over previous
#include <cuda_runtime.h>
#include <cuda_fp16.h>
#include <cstdint>

#define NPTS   65536
#define DIMS   384
#define NK     64
#define ITERS  10
#define NCH    12            // 12 chunks x 32 dims (= 2 ksteps of 16)
#define ACC_CTAS 256
#define ACC_PTS  256

typedef unsigned long long u64;

// ---------------- scratch -----------------------------------------------------
__device__ float g_centers[NK * DIMS];
// B fragments in fp16, exact mma.m16n8k16 order: [kstep s(24)][j(8)][lane(32)][word(2)]
__device__ __align__(16) unsigned short g_cfh16[24 * 8 * 32 * 2 * 2];
__device__ __align__(16) unsigned short g_cfl16[24 * 8 * 32 * 2 * 2];
__device__ float g_cc[NK];
__device__ int   g_labels[NPTS];
__device__ float g_partials[(size_t)ACC_CTAS * NK * DIMS];
__device__ float g_pcounts[NK * ACC_CTAS];
__device__ float g_proj[NK * DIMS];

// ---------------- helpers ------------------------------------------------------
__device__ __forceinline__ uint32_t h2_as_u32(__half2 h) {
    union { __half2 h; uint32_t u; } cvt;
    cvt.h = h;
    return cvt.u;
}
__device__ __forceinline__ void cp16(const void* smem, const void* gmem) {
    unsigned sa = (unsigned)__cvta_generic_to_shared(smem);
    asm volatile("cp.async.cg.shared.global [%0], [%1], 16;" :: "r"(sa), "l"(gmem));
}
__device__ __forceinline__ void cp_commit() { asm volatile("cp.async.commit_group;"); }
template <int N>
__device__ __forceinline__ void cp_wait() { asm volatile("cp.async.wait_group %0;" :: "n"(N)); }

__device__ __forceinline__ void mma16(float* d, const uint32_t* a, uint32_t b0, uint32_t b1) {
    asm("mma.sync.aligned.m16n8k16.row.col.f32.f16.f16.f32 "
        "{%0,%1,%2,%3},{%4,%5,%6,%7},{%8,%9},{%0,%1,%2,%3};"
        : "+f"(d[0]), "+f"(d[1]), "+f"(d[2]), "+f"(d[3])
        : "r"(a[0]), "r"(a[1]), "r"(a[2]), "r"(a[3]), "r"(b0), "r"(b1));
}

// B-fragment position for (cluster k, dim d), m16n8k16:
//   s=d>>4, kk=d&15, j=k>>3, t=(kk>>1)&3, lane=(k&7)*4+t, word=kk>>3, pos=kk&1
__device__ __forceinline__ void store_center_frag(int k, int d, float v) {
    const int s = d >> 4, kk = d & 15, j = k >> 3;
    const int t = (kk >> 1) & 3;
    const int lane = (k & 7) * 4 + t;
    const int word = kk >> 3, pos = kk & 1;
    const int off = ((((s * 8 + j) * 32 + lane) * 2) + word) * 2 + pos;
    const __half h = __float2half_rn(v);
    const float lof = v - __half2float(h);
    g_cfh16[off] = __half_as_ushort(h);
    g_cfl16[off] = __half_as_ushort(__float2half_rn(lof));
}

// ---------------- init centers = first 64 points ------------------------------
__global__ void init_centers_kernel(const float* __restrict__ x) {
    __shared__ float red[DIMS];
    int k = blockIdx.x, d = threadIdx.x;
    float v = x[k * DIMS + d];
    g_centers[k * DIMS + d] = v;
    store_center_frag(k, d, v);
    red[d] = v * v;
    __syncthreads();
    for (int s = 256; s > 0; s >>= 1) {
        if (d < s && d + s < DIMS) red[d] += red[d + s];
        __syncthreads();
    }
    if (d == 0) g_cc[k] = red[0];
}

// ---------------- assignment via mma.sync 3xFP16 (m16n8k16) --------------------
// 512 CTAs x 256 threads (8 warps). CTA = 128 points x 64 clusters.
// smem word(4B) offsets per buffer (stride 8192 words = 32KB):
//   A_hi [2 s][8 w][16 r][12 words(8 used + 4 pad)] : 0    .. 3072
//   A_lo                                             : 3072 .. 6144
//   B_hi [2 s][8 j][32 lane][2 words]                : 6144 .. 7168
//   B_lo                                             : 7168 .. 8192
extern __shared__ uint32_t asg_sm[];

__global__ void __launch_bounds__(256, 2) assign_kernel(const float* __restrict__ x) {
    __shared__ float scc[NK];
    const int tid = threadIdx.x;
    const int wid = tid >> 5, lane = tid & 31;
    const unsigned pcta = blockIdx.x * 128u;

    if (tid < NK) scc[tid] = g_cc[tid];

    // issue B cp.async for chunks 0 and 1 (each chunk = 1024 words per matrix)
#pragma unroll
    for (int c0 = 0; c0 < 2; ++c0) {
        uint32_t* bh = asg_sm + c0 * 8192 + 6144;
        uint32_t* bl = asg_sm + c0 * 8192 + 7168;
        const char* sh = (const char*)g_cfh16 + c0 * 4096;
        const char* sl = (const char*)g_cfl16 + c0 * 4096;
        cp16((char*)bh + tid * 16, sh + tid * 16);
        cp16((char*)bl + tid * 16, sl + tid * 16);
        cp_commit();
    }

    // prefetch x chunk 0: 4 float4 per thread
    const int ptb = tid >> 3;        // 0..31
    const int fq  = tid & 7;         // float4 index in 32-dim chunk
    float4 rx[4], rn[4];
#pragma unroll
    for (int q = 0; q < 4; ++q) {
        const int pt = ptb + 32 * q;
        rx[q] = *reinterpret_cast<const float4*>(&x[(size_t)(pcta + pt) * DIMS + fq * 4]);
    }

    float D[8][4];
#pragma unroll
    for (int j = 0; j < 8; ++j)
#pragma unroll
        for (int t = 0; t < 4; ++t) D[j][t] = 0.f;

    // producer constants
    const int sl_ = fq >> 2;             // kstep within chunk (0/1)
    const int hw  = (fq & 3) * 2;        // half2 word within row

    for (int c = 0; c < NCH; ++c) {
        const int buf = c & 1;
        uint32_t* SAH = asg_sm + buf * 8192;
        uint32_t* SAL = SAH + 3072;
        const uint32_t* SBH = SAH + 6144;
        const uint32_t* SBL = SAH + 7168;

        if (c < NCH - 2) cp_wait<1>(); else cp_wait<0>();

        // producer: split x chunk c into fp16 A fragments
#pragma unroll
        for (int q = 0; q < 4; ++q) {
            const int pt = ptb + 32 * q;
            const int w = pt >> 4, r = pt & 15;
            const int off = ((sl_ * 8 + w) * 16 + r) * 12 + hw;
            const __half2 ha = __floats2half2_rn(rx[q].x, rx[q].y);
            const __half2 hb = __floats2half2_rn(rx[q].z, rx[q].w);
            const float2 fa = __half22float2(ha);
            const float2 fb = __half22float2(hb);
            const __half2 la = __floats2half2_rn(rx[q].x - fa.x, rx[q].y - fa.y);
            const __half2 lb = __floats2half2_rn(rx[q].z - fb.x, rx[q].w - fb.y);
            *reinterpret_cast<uint2*>(SAH + off) =
                make_uint2(h2_as_u32(ha), h2_as_u32(hb));
            *reinterpret_cast<uint2*>(SAL + off) =
                make_uint2(h2_as_u32(la), h2_as_u32(lb));
        }

        // prefetch x chunk c+1
        if (c + 1 < NCH) {
#pragma unroll
            for (int q = 0; q < 4; ++q) {
                const int pt = ptb + 32 * q;
                rn[q] = *reinterpret_cast<const float4*>(
                    &x[(size_t)(pcta + pt) * DIMS + (c + 1) * 32 + fq * 4]);
            }
        }

        __syncthreads();

        // MMA: 2 ksteps x 8 ntiles x 3 (3xFP16)
        const int g = lane >> 2, t = lane & 3;
#pragma unroll
        for (int s = 0; s < 2; ++s) {
            const int ab = (s * 8 + wid) * 192;   // 16 rows * 12 words
            uint32_t a[4], al[4];
            a[0]  = SAH[ab + g * 12 + t];
            a[1]  = SAH[ab + (g + 8) * 12 + t];
            a[2]  = SAH[ab + g * 12 + t + 4];
            a[3]  = SAH[ab + (g + 8) * 12 + t + 4];
            al[0] = SAL[ab + g * 12 + t];
            al[1] = SAL[ab + (g + 8) * 12 + t];
            al[2] = SAL[ab + g * 12 + t + 4];
            al[3] = SAL[ab + (g + 8) * 12 + t + 4];
#pragma unroll
            for (int j = 0; j < 8; ++j) {
                const uint2 bh = *reinterpret_cast<const uint2*>(&SBH[((s * 8 + j) * 32 + lane) * 2]);
                const uint2 bl = *reinterpret_cast<const uint2*>(&SBL[((s * 8 + j) * 32 + lane) * 2]);
                mma16(D[j], a, bh.x, bh.y);
                mma16(D[j], a, bl.x, bl.y);
                mma16(D[j], al, bh.x, bh.y);
            }
        }
        __syncthreads();

        // issue B cp.async for chunk c+2 into this buffer
        if (c + 2 < NCH) {
            uint32_t* bh = asg_sm + buf * 8192 + 6144;
            uint32_t* bl = asg_sm + buf * 8192 + 7168;
            const char* sh = (const char*)g_cfh16 + (c + 2) * 4096;
            const char* sl = (const char*)g_cfl16 + (c + 2) * 4096;
            cp16((char*)bh + tid * 16, sh + tid * 16);
            cp16((char*)bl + tid * 16, sl + tid * 16);
            cp_commit();
        }
#pragma unroll
        for (int q = 0; q < 4; ++q) rx[q] = rn[q];
    }

    // epilogue: dist = cc[n] - 2*dot ; argmin, first-min tiebreak
    float best0 = __int_as_float(0x7f800000), best1 = best0;
    int bi0 = NK, bi1 = NK;
#pragma unroll
    for (int j = 0; j < 8; ++j) {
#pragma unroll
        for (int t = 0; t < 2; ++t) {
            const int n = j * 8 + (lane & 3) * 2 + t;
            const float cc = scc[n];
            const float s0 = fmaf(-2.0f, D[j][t], cc);
            const float s1 = fmaf(-2.0f, D[j][2 + t], cc);
            if (s0 < best0 || (s0 == best0 && n < bi0)) { best0 = s0; bi0 = n; }
            if (s1 < best1 || (s1 == best1 && n < bi1)) { best1 = s1; bi1 = n; }
        }
    }
#pragma unroll
    for (int off = 1; off < 4; off <<= 1) {
        float ob = __shfl_xor_sync(0xffffffffu, best0, off);
        int   oi = __shfl_xor_sync(0xffffffffu, bi0, off);
        if (ob < best0 || (ob == best0 && oi < bi0)) { best0 = ob; bi0 = oi; }
        ob = __shfl_xor_sync(0xffffffffu, best1, off);
        oi = __shfl_xor_sync(0xffffffffu, bi1, off);
        if (ob < best1 || (ob == best1 && oi < bi1)) { best1 = ob; bi1 = oi; }
    }
    if ((lane & 3) == 0) {
        const int r = lane >> 2;
        const unsigned p0 = pcta + wid * 16;
        g_labels[p0 + r] = bi0;
        g_labels[p0 + r + 8] = bi1;
    }
}

// ---------------- segment-sum accumulation --------------------------------------
extern __shared__ float acc_smem[];
__global__ void __launch_bounds__(384, 2) accum_kernel(const float* __restrict__ x) {
    __shared__ int s_lb[ACC_PTS];
    const int t = threadIdx.x;

    for (int i = t; i < NK * DIMS; i += 384) acc_smem[i] = 0.f;
    const int pbase = blockIdx.x * ACC_PTS;
    if (t < ACC_PTS) s_lb[t] = g_labels[pbase + t];
    __syncthreads();

    const float* xp = x + (size_t)pbase * DIMS + t;
    float cnt = 0.f;

    for (int j = 0; j < ACC_PTS; j += 32) {
        float v[32];
#pragma unroll
        for (int i = 0; i < 32; ++i)
            v[i] = __ldg(xp + (unsigned)(j + i) * DIMS);
        int lb[32];
#pragma unroll
        for (int i = 0; i < 32; ++i)
            lb[i] = s_lb[j + i];
#pragma unroll
        for (int i = 0; i < 32; ++i) {
            acc_smem[lb[i] * DIMS + t] += v[i];
            cnt += (lb[i] == t) ? 1.f : 0.f;
        }
    }
    __syncthreads();

    float* outp = g_partials + (size_t)blockIdx.x * (NK * DIMS);
    for (int i = t; i < NK * DIMS; i += 384) outp[i] = acc_smem[i];
    if (t < NK) g_pcounts[t * ACC_CTAS + blockIdx.x] = cnt;
}

// ---------------- partials reduction -> new centers ------------------------------
__global__ void __launch_bounds__(256, 4) reduce_kernel() {
    __shared__ float sp[256];
    __shared__ float sv[4][64];
    const int b = blockIdx.x;
    const int k = b / 6, dp = b % 6;
    const int t = threadIdx.x;
    const int g = t >> 6, e = t & 63;
    const int d = dp * 64 + e;

    sp[t] = g_pcounts[k * ACC_CTAS + t];

    const float* pp = g_partials + (size_t)(g * 64) * (NK * DIMS) + k * DIMS + d;
    float s = 0.f;
    for (int c = 0; c < 64; c += 16) {
#pragma unroll
        for (int i = 0; i < 16; ++i)
            s += __ldg(pp + (size_t)(c + i) * (NK * DIMS));
    }
    sv[g][e] = s;
    __syncthreads();

    for (int st = 128; st > 0; st >>= 1) {
        if (t < st) sp[t] += sp[t + st];
        __syncthreads();
    }
    const float cnt = sp[0];

    if (t < 64) {
        const float sum = ((sv[0][t] + sv[1][t]) + sv[2][t]) + sv[3][t];
        const int dd = dp * 64 + t;
        const int ee = k * DIMS + dd;
        const float v = (cnt > 0.f) ? (sum / fmaxf(cnt, 1.f)) : g_centers[ee];
        g_centers[ee] = v;
        store_center_frag(k, dd, v);
    }
}

// ---------------- finish: ||c||^2 -------------------------------------------------
__global__ void __launch_bounds__(DIMS, 1) finish_kernel() {
    __shared__ float red[DIMS];
    const int k = blockIdx.x, t = threadIdx.x;
    const float v = g_centers[k * DIMS + t];
    red[t] = v * v;
    __syncthreads();
    for (int s = 256; s > 0; s >>= 1) {
        if (t < s && t + s < DIMS) red[t] += red[t + s];
        __syncthreads();
    }
    if (t == 0) g_cc[k] = red[0];
}

// ---------------- proj = centers @ W^T + b ----------------------------------------
__global__ void proj_kernel(const float* __restrict__ W, const float* __restrict__ b) {
    __shared__ float cs[DIMS];
    const int k = blockIdx.x, d = threadIdx.x;
    cs[d] = g_centers[k * DIMS + d];
    __syncthreads();
    const float4* Wr = reinterpret_cast<const float4*>(W + (size_t)d * DIMS);
    float acc = 0.f;
#pragma unroll 4
    for (int i = 0; i < DIMS / 4; ++i) {
        const float4 w = Wr[i];
        acc += cs[4 * i] * w.x + cs[4 * i + 1] * w.y
             + cs[4 * i + 2] * w.z + cs[4 * i + 3] * w.w;
    }
    g_proj[k * DIMS + d] = acc + b[d];
}

// ---------------- scatter out[p] = proj[label[p]] ---------------------------------
__global__ void scatter_kernel(float* __restrict__ out) {
    const unsigned idx = blockIdx.x * 256u + threadIdx.x;
    const int p = idx / (DIMS / 4), r = idx % (DIMS / 4);
    const int lb = g_labels[p];
    reinterpret_cast<float4*>(out)[idx] =
        reinterpret_cast<const float4*>(g_proj)[lb * (DIMS / 4) + r];
}

// ---------------- launch ------------------------------------------------------------
extern "C" void kernel_launch(void* const* d_in, const int* in_sizes, int n_in,
                              void* d_out, int out_size) {
    const float* x = (const float*)d_in[0];
    const float* W = (const float*)d_in[1];
    const float* b = (const float*)d_in[2];
    float* out = (float*)d_out;

    const int asg_smem_bytes = 2 * 8192 * 4;                     // 65536
    const int acc_smem_bytes = NK * DIMS * (int)sizeof(float);   // 98304

    cudaFuncSetAttribute(assign_kernel, cudaFuncAttributeMaxDynamicSharedMemorySize,
                         asg_smem_bytes);
    cudaFuncSetAttribute(accum_kernel, cudaFuncAttributeMaxDynamicSharedMemorySize,
                         acc_smem_bytes);

    init_centers_kernel<<<NK, DIMS>>>(x);

    for (int it = 0; it < ITERS; ++it) {
        assign_kernel<<<NPTS / 128, 256, asg_smem_bytes>>>(x);
        accum_kernel<<<ACC_CTAS, 384, acc_smem_bytes>>>(x);
        reduce_kernel<<<6 * NK, 256>>>();
        finish_kernel<<<NK, DIMS>>>();
    }
    assign_kernel<<<NPTS / 128, 256, asg_smem_bytes>>>(x);

    proj_kernel<<<NK, DIMS>>>(W, b);
    scatter_kernel<<<(NPTS * (DIMS / 4)) / 256, 256>>>(out);
}